// round 4
// baseline (speedup 1.0000x reference)
#include <cuda_runtime.h>
#include <math.h>

#define BATCH   2
#define SEQ     2048
#define DMODEL  2048
#define NHEADS  16
#define DHEAD   128
#define MTOT    (BATCH * SEQ)   // 4096

// ---------------------------------------------------------------------------
// Scratch buffers (allocation-free rule: __device__ globals)
// ---------------------------------------------------------------------------
__device__ float g_q [(size_t)MTOT * DMODEL];
__device__ float g_k [(size_t)MTOT * DMODEL];
__device__ float g_v [(size_t)MTOT * DMODEL];
__device__ float g_ao[(size_t)MTOT * DMODEL];

// ---------------------------------------------------------------------------
// GEMM:  C[m][n] = sum_k A[m][k] * W[n][k]   (A: MTOT x K, W: N x K, row-major)
// Optional fused RoPE epilogue (for Q/K projections).
// Tiling: 128x128 CTA tile, BK=16, 256 threads, 8x8 per thread in 2x2 quadrants
// (rows {ty*4, 64+ty*4}, cols {tx*4, 64+tx*4}) so all smem reads are aligned
// float4 and conflict-free.
// ---------------------------------------------------------------------------
template<bool ROPE>
__global__ __launch_bounds__(256, 2)
void gemm_nt(const float* __restrict__ A, const float* __restrict__ W,
             float* __restrict__ C)
{
    const int N = DMODEL, K = DMODEL;
    const int BM = 128, BK = 16;

    __shared__ float As[BK][BM + 4];   // stride 132: 2-way store conflicts, clean reads
    __shared__ float Ws[BK][BM + 4];

    const int tid = threadIdx.x;
    const int tx  = tid & 15;
    const int ty  = tid >> 4;
    const int m0  = blockIdx.y * BM;
    const int n0  = blockIdx.x * BM;

    float acc[8][8];
#pragma unroll
    for (int i = 0; i < 8; i++)
#pragma unroll
        for (int j = 0; j < 8; j++) acc[i][j] = 0.f;

    const float* Ap = A + (size_t)m0 * K;
    const float* Wp = W + (size_t)n0 * K;

    const int lr = tid >> 2;            // 0..63
    const int lc = (tid & 3) << 2;      // 0,4,8,12

    for (int k0 = 0; k0 < K; k0 += BK) {
#pragma unroll
        for (int h = 0; h < 2; h++) {
            const int r = lr + h * 64;
            float4 av = *(const float4*)(Ap + (size_t)r * K + k0 + lc);
            As[lc + 0][r] = av.x; As[lc + 1][r] = av.y;
            As[lc + 2][r] = av.z; As[lc + 3][r] = av.w;
            float4 wv = *(const float4*)(Wp + (size_t)r * K + k0 + lc);
            Ws[lc + 0][r] = wv.x; Ws[lc + 1][r] = wv.y;
            Ws[lc + 2][r] = wv.z; Ws[lc + 3][r] = wv.w;
        }
        __syncthreads();

#pragma unroll
        for (int kk = 0; kk < BK; kk++) {
            float4 a0 = *(const float4*)&As[kk][ty * 4];
            float4 a1 = *(const float4*)&As[kk][64 + ty * 4];
            float4 b0 = *(const float4*)&Ws[kk][tx * 4];
            float4 b1 = *(const float4*)&Ws[kk][64 + tx * 4];
            float ra[8] = {a0.x, a0.y, a0.z, a0.w, a1.x, a1.y, a1.z, a1.w};
            float rb[8] = {b0.x, b0.y, b0.z, b0.w, b1.x, b1.y, b1.z, b1.w};
#pragma unroll
            for (int i = 0; i < 8; i++)
#pragma unroll
                for (int j = 0; j < 8; j++)
                    acc[i][j] = fmaf(ra[i], rb[j], acc[i][j]);
        }
        __syncthreads();
    }

    // ----- epilogue (optionally fused RoPE) -----
#pragma unroll
    for (int qj = 0; qj < 2; qj++) {
        const int cb = qj * 64 + tx * 4;        // 0..124, multiple of 4
        float inv0 = 0.f, inv1 = 0.f;
        if (ROPE) {
            // head-dim index d = (n0 + cb + j) & 127 == cb + j (n0 % 128 == 0)
            const float fi0 = (float)(cb >> 1);  // pair index of (cb, cb+1)
            inv0 = powf(10000.f, -2.f * fi0        / (float)DHEAD);
            inv1 = powf(10000.f, -2.f * (fi0 + 1.f) / (float)DHEAD);
        }
#pragma unroll
        for (int qi = 0; qi < 2; qi++) {
#pragma unroll
            for (int i = 0; i < 4; i++) {
                const int m = m0 + qi * 64 + ty * 4 + i;
                float v0 = acc[qi * 4 + i][qj * 4 + 0];
                float v1 = acc[qi * 4 + i][qj * 4 + 1];
                float v2 = acc[qi * 4 + i][qj * 4 + 2];
                float v3 = acc[qi * 4 + i][qj * 4 + 3];
                if (ROPE) {
                    const float s = (float)(m & (SEQ - 1));
                    float sn, cs;
                    sincosf(s * inv0, &sn, &cs);
                    float e = v0, o = v1;
                    v0 = e * cs - o * sn;
                    v1 = e * sn + o * cs;
                    sincosf(s * inv1, &sn, &cs);
                    e = v2; o = v3;
                    v2 = e * cs - o * sn;
                    v3 = e * sn + o * cs;
                }
                float4 outv = make_float4(v0, v1, v2, v3);
                *(float4*)(C + (size_t)m * N + n0 + cb) = outv;
            }
        }
    }
}

// ---------------------------------------------------------------------------
// Flash attention (causal), fp32.
// Grid: (SEQ/64, NHEADS, BATCH). 256 threads = 16x16 grid.
// Per CTA: 64 query rows x full head (d=128). KV tiles of 64.
// Smem: Qs/Ks transposed [d][kv] with stride 68 (aligned float4 reads,
//       conflict-free in hot loop), Vs row-major [kv][d], Ps [r][kv] stride 65
//       (broadcast reads in PV).
// ---------------------------------------------------------------------------
#define QS_STRIDE 68
#define PS_STRIDE 65
#define ATTN_SMEM ((128*QS_STRIDE + 128*QS_STRIDE + 64*DHEAD + 64*PS_STRIDE) * (int)sizeof(float))

__global__ __launch_bounds__(256, 1)
void attn_kernel(const float* __restrict__ Q, const float* __restrict__ Kg,
                 const float* __restrict__ V, float* __restrict__ O)
{
    const int BQ = 64, BKV = 64;
    extern __shared__ float sm[];
    float* Qs = sm;                                 // [128][68]  Qs[d*68 + r]
    float* Ks = Qs + 128 * QS_STRIDE;               // [128][68]  Ks[d*68 + c]
    float* Vs = Ks + 128 * QS_STRIDE;               // [64][128]  Vs[c*128 + d]
    float* Ps = Vs + 64 * DHEAD;                    // [64][65]   Ps[r*65 + c]

    const int tid = threadIdx.x;
    const int tx  = tid & 15;
    const int ty  = tid >> 4;
    const int qt  = blockIdx.x;
    const int h   = blockIdx.y;
    const int b   = blockIdx.z;
    const int q0  = qt * BQ;

    const size_t rowbase = (size_t)b * SEQ * DMODEL + (size_t)h * DHEAD;

    // Load Q tile transposed (coalesced global reads, 4-way STS conflicts, once)
    for (int idx = tid; idx < BQ * DHEAD; idx += 256) {
        const int r = idx >> 7;          // 0..63
        const int d = idx & 127;
        Qs[d * QS_STRIDE + r] = Q[rowbase + (size_t)(q0 + r) * DMODEL + d];
    }

    float accO[4][8];
    float mrow[4], lrow[4];
#pragma unroll
    for (int i = 0; i < 4; i++) {
        mrow[i] = -1e30f;
        lrow[i] = 0.f;
#pragma unroll
        for (int j = 0; j < 8; j++) accO[i][j] = 0.f;
    }

    const float scale = 0.08838834764831845f;   // 1/sqrt(128)

    for (int kt = 0; kt <= qt; kt++) {
        const int kv0 = kt * BKV;

        // Load K (transposed) and V (row-major) tiles
        for (int idx = tid; idx < BKV * DHEAD; idx += 256) {
            const int c = idx >> 7;
            const int d = idx & 127;
            const float kvval = Kg[rowbase + (size_t)(kv0 + c) * DMODEL + d];
            Ks[d * QS_STRIDE + c] = kvval;
            Vs[c * DHEAD + d]     = V[rowbase + (size_t)(kv0 + c) * DMODEL + d];
        }
        __syncthreads();

        // Scores: 64x64 = Q(64x128) . K^T  -- each thread 4x4
        float sc[4][4];
#pragma unroll
        for (int i = 0; i < 4; i++)
#pragma unroll
            for (int j = 0; j < 4; j++) sc[i][j] = 0.f;

        const float* qp = Qs + ty * 4;
        const float* kp = Ks + tx * 4;
#pragma unroll 16
        for (int k = 0; k < DHEAD; k++) {
            float4 qv = *(const float4*)(qp + k * QS_STRIDE);
            float4 kv = *(const float4*)(kp + k * QS_STRIDE);
            float ra[4] = {qv.x, qv.y, qv.z, qv.w};
            float rb[4] = {kv.x, kv.y, kv.z, kv.w};
#pragma unroll
            for (int i = 0; i < 4; i++)
#pragma unroll
                for (int j = 0; j < 4; j++)
                    sc[i][j] = fmaf(ra[i], rb[j], sc[i][j]);
        }

        // Online softmax (row groups reduce across the 16 tx lanes)
        const bool diag = (kt == qt);
#pragma unroll
        for (int i = 0; i < 4; i++) {
            const int r = q0 + ty * 4 + i;
            float sv[4];
#pragma unroll
            for (int j = 0; j < 4; j++) {
                float s = sc[i][j] * scale;
                if (diag && (kv0 + tx * 4 + j > r)) s = -1e30f;
                sv[j] = s;
            }
            float mloc = fmaxf(fmaxf(sv[0], sv[1]), fmaxf(sv[2], sv[3]));
            mloc = fmaxf(mloc, __shfl_xor_sync(0xffffffffu, mloc, 1));
            mloc = fmaxf(mloc, __shfl_xor_sync(0xffffffffu, mloc, 2));
            mloc = fmaxf(mloc, __shfl_xor_sync(0xffffffffu, mloc, 4));
            mloc = fmaxf(mloc, __shfl_xor_sync(0xffffffffu, mloc, 8));
            const float mnew  = fmaxf(mrow[i], mloc);
            const float alpha = __expf(mrow[i] - mnew);
            float ls = 0.f;
#pragma unroll
            for (int j = 0; j < 4; j++) {
                const float p = __expf(sv[j] - mnew);
                Ps[(ty * 4 + i) * PS_STRIDE + tx * 4 + j] = p;
                ls += p;
            }
            ls += __shfl_xor_sync(0xffffffffu, ls, 1);
            ls += __shfl_xor_sync(0xffffffffu, ls, 2);
            ls += __shfl_xor_sync(0xffffffffu, ls, 4);
            ls += __shfl_xor_sync(0xffffffffu, ls, 8);
            lrow[i] = lrow[i] * alpha + ls;
            mrow[i] = mnew;
#pragma unroll
            for (int j = 0; j < 8; j++) accO[i][j] *= alpha;
        }
        __syncthreads();

        // PV: O(64x128) += P(64x64) . V(64x128) -- each thread 4 rows x 8 cols
        const float* vp = Vs + tx * 4;
#pragma unroll 8
        for (int c = 0; c < BKV; c++) {
            float4 v0 = *(const float4*)(vp + c * DHEAD);
            float4 v1 = *(const float4*)(vp + c * DHEAD + 64);
#pragma unroll
            for (int i = 0; i < 4; i++) {
                const float p = Ps[(ty * 4 + i) * PS_STRIDE + c];
                accO[i][0] = fmaf(p, v0.x, accO[i][0]);
                accO[i][1] = fmaf(p, v0.y, accO[i][1]);
                accO[i][2] = fmaf(p, v0.z, accO[i][2]);
                accO[i][3] = fmaf(p, v0.w, accO[i][3]);
                accO[i][4] = fmaf(p, v1.x, accO[i][4]);
                accO[i][5] = fmaf(p, v1.y, accO[i][5]);
                accO[i][6] = fmaf(p, v1.z, accO[i][6]);
                accO[i][7] = fmaf(p, v1.w, accO[i][7]);
            }
        }
        __syncthreads();   // protect Ks/Vs/Ps before next iteration's loads
    }

    // Normalize and store (layout: (b, s, h, d) flattened to (B*S, DMODEL))
#pragma unroll
    for (int i = 0; i < 4; i++) {
        const float inv = 1.f / lrow[i];
        const size_t orow = rowbase + (size_t)(q0 + ty * 4 + i) * DMODEL;
        float4 o0 = make_float4(accO[i][0] * inv, accO[i][1] * inv,
                                accO[i][2] * inv, accO[i][3] * inv);
        float4 o1 = make_float4(accO[i][4] * inv, accO[i][5] * inv,
                                accO[i][6] * inv, accO[i][7] * inv);
        *(float4*)(O + orow + tx * 4)      = o0;
        *(float4*)(O + orow + 64 + tx * 4) = o1;
    }
}

// ---------------------------------------------------------------------------
// Launch
// ---------------------------------------------------------------------------
extern "C" void kernel_launch(void* const* d_in, const int* in_sizes, int n_in,
                              void* d_out, int out_size)
{
    const float* x  = (const float*)d_in[0];
    const float* wq = (const float*)d_in[1];
    const float* wk = (const float*)d_in[2];
    const float* wv = (const float*)d_in[3];
    const float* wo = (const float*)d_in[4];
    float* out = (float*)d_out;

    float *q, *k, *v, *ao;
    cudaGetSymbolAddress((void**)&q,  g_q);
    cudaGetSymbolAddress((void**)&k,  g_k);
    cudaGetSymbolAddress((void**)&v,  g_v);
    cudaGetSymbolAddress((void**)&ao, g_ao);

    dim3 gg(DMODEL / 128, MTOT / 128);   // (16, 32)

    gemm_nt<true ><<<gg, 256>>>(x, wq, q);   // Q projection + RoPE
    gemm_nt<true ><<<gg, 256>>>(x, wk, k);   // K projection + RoPE
    gemm_nt<false><<<gg, 256>>>(x, wv, v);   // V projection

    cudaFuncSetAttribute(attn_kernel,
                         cudaFuncAttributeMaxDynamicSharedMemorySize, ATTN_SMEM);
    attn_kernel<<<dim3(SEQ / 64, NHEADS, BATCH), 256, ATTN_SMEM>>>(q, k, v, ao);

    gemm_nt<false><<<gg, 256>>>(ao, wo, out);  // output projection
}

// round 10
// speedup vs baseline: 1.2662x; 1.2662x over previous
#include <cuda_runtime.h>
#include <cuda_fp16.h>
#include <math.h>
#include <stdint.h>

#define BATCH   2
#define SEQ     2048
#define DMODEL  2048
#define NHEADS  16
#define DHEAD   128
#define MTOT    (BATCH * SEQ)   // 4096

// ---------------------------------------------------------------------------
// Scratch buffers (allocation-free rule: __device__ globals)
// ---------------------------------------------------------------------------
__device__ float g_q [(size_t)MTOT * DMODEL];
__device__ float g_k [(size_t)MTOT * DMODEL];
__device__ float g_v [(size_t)MTOT * DMODEL];
__device__ float g_ao[(size_t)MTOT * DMODEL];

// ---------------------------------------------------------------------------
// Warp-MMA helpers (baseline-family PTX only: ldmatrix sm_75+, mma sm_80+)
// ---------------------------------------------------------------------------
__device__ __forceinline__ uint32_t smem_u32(const void* p) {
    uint32_t a;
    asm("{ .reg .u64 t; cvta.to.shared.u64 t, %1; cvt.u32.u64 %0, t; }"
        : "=r"(a) : "l"(p));
    return a;
}

__device__ __forceinline__ void ldsm_x4(uint32_t addr, uint32_t& r0, uint32_t& r1,
                                        uint32_t& r2, uint32_t& r3) {
    asm volatile("ldmatrix.sync.aligned.m8n8.x4.shared.b16 {%0,%1,%2,%3}, [%4];"
                 : "=r"(r0), "=r"(r1), "=r"(r2), "=r"(r3) : "r"(addr));
}

__device__ __forceinline__ void mma16816(float* d, const uint32_t* a,
                                         uint32_t b0, uint32_t b1) {
    asm volatile("mma.sync.aligned.m16n8k16.row.col.f32.f16.f16.f32 "
                 "{%0,%1,%2,%3}, {%4,%5,%6,%7}, {%8,%9}, {%0,%1,%2,%3};"
                 : "+f"(d[0]), "+f"(d[1]), "+f"(d[2]), "+f"(d[3])
                 : "r"(a[0]), "r"(a[1]), "r"(a[2]), "r"(a[3]), "r"(b0), "r"(b1));
}

// ---------------------------------------------------------------------------
// HMMA fp16 GEMM:  C[m][n] = sum_k A[m][k] * W[n][k]   (both K-major, NT)
// 128x128 CTA tile, 8 warps (4x2 -> warp tile 32x64), BK=32, double-buffered
// smem, fp32->fp16 convert at load, fp32 accumulate. Optional fused RoPE.
// Smem rows padded to 40 halves: all ldmatrix lane addresses conflict-free.
// ---------------------------------------------------------------------------
#define BK      32
#define NCH     (DMODEL / BK)    // 64
#define LDS_ROW 40               // halves per smem row (32 + 8 pad)

template<bool ROPE>
__global__ __launch_bounds__(256, 2)
void gemm_hmma(const float* __restrict__ A, const float* __restrict__ W,
               float* __restrict__ C)
{
    __shared__ __align__(16) __half smA[2][128 * LDS_ROW];
    __shared__ __align__(16) __half smW[2][128 * LDS_ROW];

    const int tid = threadIdx.x;
    const int wid = tid >> 5;
    const int lid = tid & 31;
    const int wm  = wid >> 1;            // 0..3  (warp row -> 32 m-rows)
    const int wn  = wid & 1;             // 0..1  (warp col -> 64 n-cols)
    const int m0  = blockIdx.y * 128;
    const int n0  = blockIdx.x * 128;

    // ---- per-thread load slice: row r (0..127), 16 cols at side*16 ----
    const int r    = tid >> 1;
    const int side = tid & 1;
    const float* Ap = A + (size_t)(m0 + r) * DMODEL + side * 16;
    const float* Wp = W + (size_t)(n0 + r) * DMODEL + side * 16;
    __half* stA = &smA[0][0] + r * LDS_ROW + side * 16;   // stage 0 base
    __half* stW = &smW[0][0] + r * LDS_ROW + side * 16;
    const int stageH = 128 * LDS_ROW;                      // halves per stage

    // ---- ldmatrix lane offsets (bytes), for ks=0; ks=16 adds 32B ----
    const uint32_t baseA = smem_u32(&smA[0][0]);
    const uint32_t baseW = smem_u32(&smW[0][0]);
    uint32_t offA[2], offB[4];
#pragma unroll
    for (int mt = 0; mt < 2; mt++) {
        const int row = wm * 32 + mt * 16 + (lid & 15);
        const int col = (lid >> 4) << 3;
        offA[mt] = (uint32_t)((row * LDS_ROW + col) * 2);
    }
#pragma unroll
    for (int nb = 0; nb < 4; nb++) {
        const int row = wn * 64 + nb * 16 + (lid & 7) + ((lid & 16) ? 8 : 0);
        const int col = (lid & 8) ? 8 : 0;
        offB[nb] = (uint32_t)((row * LDS_ROW + col) * 2);
    }

    float acc[2][8][4];
#pragma unroll
    for (int mt = 0; mt < 2; mt++)
#pragma unroll
        for (int nt = 0; nt < 8; nt++)
#pragma unroll
            for (int i = 0; i < 4; i++) acc[mt][nt][i] = 0.f;

    // load 16 fp32 -> 8 packed half2 regs
    auto ldcvt = [](const float* src, uint32_t* u) {
#pragma unroll
        for (int i = 0; i < 4; i++) {
            float4 v = *(const float4*)(src + i * 4);
            __half2 h0 = __floats2half2_rn(v.x, v.y);
            __half2 h1 = __floats2half2_rn(v.z, v.w);
            u[i * 2 + 0] = *reinterpret_cast<uint32_t*>(&h0);
            u[i * 2 + 1] = *reinterpret_cast<uint32_t*>(&h1);
        }
    };
    auto st16 = [](__half* dst, const uint32_t* u) {
        *reinterpret_cast<uint4*>(dst)     = make_uint4(u[0], u[1], u[2], u[3]);
        *reinterpret_cast<uint4*>(dst + 8) = make_uint4(u[4], u[5], u[6], u[7]);
    };

    uint32_t ua[8], uw[8];

    // ---- prologue: chunk 0 into stage 0 ----
    ldcvt(Ap, ua); st16(stA, ua);
    ldcvt(Wp, uw); st16(stW, uw);
    __syncthreads();

    for (int c = 0; c < NCH; c++) {
        const int s = c & 1;
        const bool more = (c + 1 < NCH);
        const uint32_t sA = baseA + (uint32_t)(s * stageH * 2);
        const uint32_t sW = baseW + (uint32_t)(s * stageH * 2);
        __half* nA = stA + (s ^ 1) * stageH;
        __half* nW = stW + (s ^ 1) * stageH;

        if (more) ldcvt(Ap + (c + 1) * BK, ua);

        // ---- k-step 0 ----
        {
            uint32_t a[2][4], b[4][4];
#pragma unroll
            for (int mt = 0; mt < 2; mt++)
                ldsm_x4(sA + offA[mt], a[mt][0], a[mt][1], a[mt][2], a[mt][3]);
#pragma unroll
            for (int nb = 0; nb < 4; nb++)
                ldsm_x4(sW + offB[nb], b[nb][0], b[nb][1], b[nb][2], b[nb][3]);
#pragma unroll
            for (int mt = 0; mt < 2; mt++)
#pragma unroll
                for (int nb = 0; nb < 4; nb++) {
                    mma16816(acc[mt][2 * nb],     a[mt], b[nb][0], b[nb][1]);
                    mma16816(acc[mt][2 * nb + 1], a[mt], b[nb][2], b[nb][3]);
                }
        }

        if (more) { st16(nA, ua); ldcvt(Wp + (c + 1) * BK, uw); }

        // ---- k-step 1 (cols +16 halves = +32B) ----
        {
            uint32_t a[2][4], b[4][4];
#pragma unroll
            for (int mt = 0; mt < 2; mt++)
                ldsm_x4(sA + offA[mt] + 32, a[mt][0], a[mt][1], a[mt][2], a[mt][3]);
#pragma unroll
            for (int nb = 0; nb < 4; nb++)
                ldsm_x4(sW + offB[nb] + 32, b[nb][0], b[nb][1], b[nb][2], b[nb][3]);
#pragma unroll
            for (int mt = 0; mt < 2; mt++)
#pragma unroll
                for (int nb = 0; nb < 4; nb++) {
                    mma16816(acc[mt][2 * nb],     a[mt], b[nb][0], b[nb][1]);
                    mma16816(acc[mt][2 * nb + 1], a[mt], b[nb][2], b[nb][3]);
                }
        }

        if (more) st16(nW, uw);
        __syncthreads();
    }

    // ---- epilogue: C fragment (row t/4 & +8, col pair 2(t%4)) + RoPE ----
    const int qr = lid >> 2;
    const int qc = (lid & 3) * 2;

    float inv[8];
    if (ROPE) {
#pragma unroll
        for (int nt = 0; nt < 8; nt++) {
            const int d = wn * 64 + nt * 8 + qc;          // even head-dim index
            inv[nt] = powf(10000.f, -(float)d * (1.f / 128.f));
        }
    }

#pragma unroll
    for (int mt = 0; mt < 2; mt++) {
#pragma unroll
        for (int h = 0; h < 2; h++) {
            const int m = m0 + wm * 32 + mt * 16 + qr + h * 8;
            float* crow = C + (size_t)m * DMODEL + n0;
            const float pos = (float)(m & (SEQ - 1));
#pragma unroll
            for (int nt = 0; nt < 8; nt++) {
                float e = acc[mt][nt][2 * h + 0];
                float o = acc[mt][nt][2 * h + 1];
                if (ROPE) {
                    float sn, cs;
                    sincosf(pos * inv[nt], &sn, &cs);
                    const float e2 = e * cs - o * sn;
                    o = e * sn + o * cs;
                    e = e2;
                }
                *(float2*)(crow + wn * 64 + nt * 8 + qc) = make_float2(e, o);
            }
        }
    }
}

// ---------------------------------------------------------------------------
// Flash attention (causal), fp32 — unchanged (passed at rel_err 3.9e-6).
// ---------------------------------------------------------------------------
#define QS_STRIDE 68
#define PS_STRIDE 65
#define ATTN_SMEM ((128*QS_STRIDE + 128*QS_STRIDE + 64*DHEAD + 64*PS_STRIDE) * (int)sizeof(float))

__global__ __launch_bounds__(256, 1)
void attn_kernel(const float* __restrict__ Q, const float* __restrict__ Kg,
                 const float* __restrict__ V, float* __restrict__ O)
{
    const int BQ = 64, BKV = 64;
    extern __shared__ float sm[];
    float* Qs = sm;
    float* Ks = Qs + 128 * QS_STRIDE;
    float* Vs = Ks + 128 * QS_STRIDE;
    float* Ps = Vs + 64 * DHEAD;

    const int tid = threadIdx.x;
    const int tx  = tid & 15;
    const int ty  = tid >> 4;
    const int qt  = blockIdx.x;
    const int h   = blockIdx.y;
    const int b   = blockIdx.z;
    const int q0  = qt * BQ;

    const size_t rowbase = (size_t)b * SEQ * DMODEL + (size_t)h * DHEAD;

    for (int idx = tid; idx < BQ * DHEAD; idx += 256) {
        const int r = idx >> 7;
        const int d = idx & 127;
        Qs[d * QS_STRIDE + r] = Q[rowbase + (size_t)(q0 + r) * DMODEL + d];
    }

    float accO[4][8];
    float mrow[4], lrow[4];
#pragma unroll
    for (int i = 0; i < 4; i++) {
        mrow[i] = -1e30f;
        lrow[i] = 0.f;
#pragma unroll
        for (int j = 0; j < 8; j++) accO[i][j] = 0.f;
    }

    const float scale = 0.08838834764831845f;

    for (int kt = 0; kt <= qt; kt++) {
        const int kv0 = kt * BKV;

        for (int idx = tid; idx < BKV * DHEAD; idx += 256) {
            const int c = idx >> 7;
            const int d = idx & 127;
            const float kvval = Kg[rowbase + (size_t)(kv0 + c) * DMODEL + d];
            Ks[d * QS_STRIDE + c] = kvval;
            Vs[c * DHEAD + d]     = V[rowbase + (size_t)(kv0 + c) * DMODEL + d];
        }
        __syncthreads();

        float sc[4][4];
#pragma unroll
        for (int i = 0; i < 4; i++)
#pragma unroll
            for (int j = 0; j < 4; j++) sc[i][j] = 0.f;

        const float* qp = Qs + ty * 4;
        const float* kp = Ks + tx * 4;
#pragma unroll 16
        for (int k = 0; k < DHEAD; k++) {
            float4 qv = *(const float4*)(qp + k * QS_STRIDE);
            float4 kv = *(const float4*)(kp + k * QS_STRIDE);
            float ra[4] = {qv.x, qv.y, qv.z, qv.w};
            float rb[4] = {kv.x, kv.y, kv.z, kv.w};
#pragma unroll
            for (int i = 0; i < 4; i++)
#pragma unroll
                for (int j = 0; j < 4; j++)
                    sc[i][j] = fmaf(ra[i], rb[j], sc[i][j]);
        }

        const bool diag = (kt == qt);
#pragma unroll
        for (int i = 0; i < 4; i++) {
            const int rr = q0 + ty * 4 + i;
            float sv[4];
#pragma unroll
            for (int j = 0; j < 4; j++) {
                float s = sc[i][j] * scale;
                if (diag && (kv0 + tx * 4 + j > rr)) s = -1e30f;
                sv[j] = s;
            }
            float mloc = fmaxf(fmaxf(sv[0], sv[1]), fmaxf(sv[2], sv[3]));
            mloc = fmaxf(mloc, __shfl_xor_sync(0xffffffffu, mloc, 1));
            mloc = fmaxf(mloc, __shfl_xor_sync(0xffffffffu, mloc, 2));
            mloc = fmaxf(mloc, __shfl_xor_sync(0xffffffffu, mloc, 4));
            mloc = fmaxf(mloc, __shfl_xor_sync(0xffffffffu, mloc, 8));
            const float mnew  = fmaxf(mrow[i], mloc);
            const float alpha = __expf(mrow[i] - mnew);
            float ls = 0.f;
#pragma unroll
            for (int j = 0; j < 4; j++) {
                const float p = __expf(sv[j] - mnew);
                Ps[(ty * 4 + i) * PS_STRIDE + tx * 4 + j] = p;
                ls += p;
            }
            ls += __shfl_xor_sync(0xffffffffu, ls, 1);
            ls += __shfl_xor_sync(0xffffffffu, ls, 2);
            ls += __shfl_xor_sync(0xffffffffu, ls, 4);
            ls += __shfl_xor_sync(0xffffffffu, ls, 8);
            lrow[i] = lrow[i] * alpha + ls;
            mrow[i] = mnew;
#pragma unroll
            for (int j = 0; j < 8; j++) accO[i][j] *= alpha;
        }
        __syncthreads();

        const float* vp = Vs + tx * 4;
#pragma unroll 8
        for (int c = 0; c < BKV; c++) {
            float4 v0 = *(const float4*)(vp + c * DHEAD);
            float4 v1 = *(const float4*)(vp + c * DHEAD + 64);
#pragma unroll
            for (int i = 0; i < 4; i++) {
                const float p = Ps[(ty * 4 + i) * PS_STRIDE + c];
                accO[i][0] = fmaf(p, v0.x, accO[i][0]);
                accO[i][1] = fmaf(p, v0.y, accO[i][1]);
                accO[i][2] = fmaf(p, v0.z, accO[i][2]);
                accO[i][3] = fmaf(p, v0.w, accO[i][3]);
                accO[i][4] = fmaf(p, v1.x, accO[i][4]);
                accO[i][5] = fmaf(p, v1.y, accO[i][5]);
                accO[i][6] = fmaf(p, v1.z, accO[i][6]);
                accO[i][7] = fmaf(p, v1.w, accO[i][7]);
            }
        }
        __syncthreads();
    }

#pragma unroll
    for (int i = 0; i < 4; i++) {
        const float inv = 1.f / lrow[i];
        const size_t orow = rowbase + (size_t)(q0 + ty * 4 + i) * DMODEL;
        float4 o0 = make_float4(accO[i][0] * inv, accO[i][1] * inv,
                                accO[i][2] * inv, accO[i][3] * inv);
        float4 o1 = make_float4(accO[i][4] * inv, accO[i][5] * inv,
                                accO[i][6] * inv, accO[i][7] * inv);
        *(float4*)(O + orow + tx * 4)      = o0;
        *(float4*)(O + orow + 64 + tx * 4) = o1;
    }
}

// ---------------------------------------------------------------------------
// Launch
// ---------------------------------------------------------------------------
extern "C" void kernel_launch(void* const* d_in, const int* in_sizes, int n_in,
                              void* d_out, int out_size)
{
    const float* x  = (const float*)d_in[0];
    const float* wq = (const float*)d_in[1];
    const float* wk = (const float*)d_in[2];
    const float* wv = (const float*)d_in[3];
    const float* wo = (const float*)d_in[4];
    float* out = (float*)d_out;

    float *q, *k, *v, *ao;
    cudaGetSymbolAddress((void**)&q,  g_q);
    cudaGetSymbolAddress((void**)&k,  g_k);
    cudaGetSymbolAddress((void**)&v,  g_v);
    cudaGetSymbolAddress((void**)&ao, g_ao);

    cudaFuncSetAttribute(attn_kernel,
                         cudaFuncAttributeMaxDynamicSharedMemorySize, ATTN_SMEM);

    dim3 gg(DMODEL / 128, MTOT / 128);   // (16, 32)

    gemm_hmma<true ><<<gg, 256>>>(x, wq, q);   // Q projection + RoPE
    gemm_hmma<true ><<<gg, 256>>>(x, wk, k);   // K projection + RoPE
    gemm_hmma<false><<<gg, 256>>>(x, wv, v);   // V projection

    attn_kernel<<<dim3(SEQ / 64, NHEADS, BATCH), 256, ATTN_SMEM>>>(q, k, v, ao);

    gemm_hmma<false><<<gg, 256>>>(ao, wo, out);  // output projection
}

// round 12
// speedup vs baseline: 3.6607x; 2.8911x over previous
#include <cuda_runtime.h>
#include <cuda_fp16.h>
#include <math.h>
#include <stdint.h>

#define BATCH   2
#define SEQ     2048
#define DMODEL  2048
#define NHEADS  16
#define DHEAD   128
#define MTOT    (BATCH * SEQ)   // 4096

// ---------------------------------------------------------------------------
// Scratch buffers (allocation-free rule: __device__ globals) — fp16 dataflow
// ---------------------------------------------------------------------------
__device__ __half g_qh [(size_t)MTOT * DMODEL];
__device__ __half g_kh [(size_t)MTOT * DMODEL];
__device__ __half g_vh [(size_t)MTOT * DMODEL];
__device__ __half g_aoh[(size_t)MTOT * DMODEL];

// ---------------------------------------------------------------------------
// Warp-MMA helpers (baseline-family PTX only: ldmatrix sm_75+, mma sm_80+)
// ---------------------------------------------------------------------------
__device__ __forceinline__ uint32_t smem_u32(const void* p) {
    uint32_t a;
    asm("{ .reg .u64 t; cvta.to.shared.u64 t, %1; cvt.u32.u64 %0, t; }"
        : "=r"(a) : "l"(p));
    return a;
}

__device__ __forceinline__ void ldsm_x4(uint32_t addr, uint32_t& r0, uint32_t& r1,
                                        uint32_t& r2, uint32_t& r3) {
    asm volatile("ldmatrix.sync.aligned.m8n8.x4.shared.b16 {%0,%1,%2,%3}, [%4];"
                 : "=r"(r0), "=r"(r1), "=r"(r2), "=r"(r3) : "r"(addr));
}

__device__ __forceinline__ void ldsm_x4_t(uint32_t addr, uint32_t& r0, uint32_t& r1,
                                          uint32_t& r2, uint32_t& r3) {
    asm volatile("ldmatrix.sync.aligned.m8n8.x4.trans.shared.b16 {%0,%1,%2,%3}, [%4];"
                 : "=r"(r0), "=r"(r1), "=r"(r2), "=r"(r3) : "r"(addr));
}

__device__ __forceinline__ void mma16816(float* d, const uint32_t* a,
                                         uint32_t b0, uint32_t b1) {
    asm volatile("mma.sync.aligned.m16n8k16.row.col.f32.f16.f16.f32 "
                 "{%0,%1,%2,%3}, {%4,%5,%6,%7}, {%8,%9}, {%0,%1,%2,%3};"
                 : "+f"(d[0]), "+f"(d[1]), "+f"(d[2]), "+f"(d[3])
                 : "r"(a[0]), "r"(a[1]), "r"(a[2]), "r"(a[3]), "r"(b0), "r"(b1));
}

__device__ __forceinline__ float fast_exp2(float x) {
    float y;
    asm("ex2.approx.ftz.f32 %0, %1;" : "=f"(y) : "f"(x));
    return y;
}

// load 16 source elems -> 8 packed half2 regs
__device__ __forceinline__ void load_frag(const float* src, uint32_t* u) {
#pragma unroll
    for (int i = 0; i < 4; i++) {
        float4 v = *(const float4*)(src + i * 4);
        __half2 h0 = __floats2half2_rn(v.x, v.y);
        __half2 h1 = __floats2half2_rn(v.z, v.w);
        u[i * 2 + 0] = *reinterpret_cast<uint32_t*>(&h0);
        u[i * 2 + 1] = *reinterpret_cast<uint32_t*>(&h1);
    }
}
__device__ __forceinline__ void load_frag(const __half* src, uint32_t* u) {
    uint4 v0 = *(const uint4*)src;
    uint4 v1 = *(const uint4*)(src + 8);
    u[0] = v0.x; u[1] = v0.y; u[2] = v0.z; u[3] = v0.w;
    u[4] = v1.x; u[5] = v1.y; u[6] = v1.z; u[7] = v1.w;
}

// ---------------------------------------------------------------------------
// HMMA fp16 GEMM:  C[m][n] = sum_k A[m][k] * W[n][k]   (both K-major, NT)
// 128x128 CTA tile, 8 warps (4x2 -> warp tile 32x64), BK=32, double-buffered.
// TA = float|__half input A; HOUT: write fp16 (for attention) or fp32.
// ---------------------------------------------------------------------------
#define BK      32
#define NCH     (DMODEL / BK)    // 64
#define LDS_ROW 40               // halves per smem row (32 + 8 pad)

template<bool ROPE, bool HOUT, typename TA>
__global__ __launch_bounds__(256, 2)
void gemm_hmma(const TA* __restrict__ A, const float* __restrict__ W,
               void* __restrict__ Cv)
{
    __shared__ __align__(16) __half smA[2][128 * LDS_ROW];
    __shared__ __align__(16) __half smW[2][128 * LDS_ROW];

    const int tid = threadIdx.x;
    const int wid = tid >> 5;
    const int lid = tid & 31;
    const int wm  = wid >> 1;
    const int wn  = wid & 1;
    const int m0  = blockIdx.y * 128;
    const int n0  = blockIdx.x * 128;

    const int r    = tid >> 1;
    const int side = tid & 1;
    const TA*    Ap = A + (size_t)(m0 + r) * DMODEL + side * 16;
    const float* Wp = W + (size_t)(n0 + r) * DMODEL + side * 16;
    __half* stA = &smA[0][0] + r * LDS_ROW + side * 16;
    __half* stW = &smW[0][0] + r * LDS_ROW + side * 16;
    const int stageH = 128 * LDS_ROW;

    const uint32_t baseA = smem_u32(&smA[0][0]);
    const uint32_t baseW = smem_u32(&smW[0][0]);
    uint32_t offA[2], offB[4];
#pragma unroll
    for (int mt = 0; mt < 2; mt++) {
        const int row = wm * 32 + mt * 16 + (lid & 15);
        const int col = (lid >> 4) << 3;
        offA[mt] = (uint32_t)((row * LDS_ROW + col) * 2);
    }
#pragma unroll
    for (int nb = 0; nb < 4; nb++) {
        const int row = wn * 64 + nb * 16 + (lid & 7) + ((lid & 16) ? 8 : 0);
        const int col = (lid & 8) ? 8 : 0;
        offB[nb] = (uint32_t)((row * LDS_ROW + col) * 2);
    }

    float acc[2][8][4];
#pragma unroll
    for (int mt = 0; mt < 2; mt++)
#pragma unroll
        for (int nt = 0; nt < 8; nt++)
#pragma unroll
            for (int i = 0; i < 4; i++) acc[mt][nt][i] = 0.f;

    auto st16 = [](__half* dst, const uint32_t* u) {
        *reinterpret_cast<uint4*>(dst)     = make_uint4(u[0], u[1], u[2], u[3]);
        *reinterpret_cast<uint4*>(dst + 8) = make_uint4(u[4], u[5], u[6], u[7]);
    };

    uint32_t ua[8], uw[8];
    load_frag(Ap, ua); st16(stA, ua);
    load_frag(Wp, uw); st16(stW, uw);
    __syncthreads();

    for (int c = 0; c < NCH; c++) {
        const int s = c & 1;
        const bool more = (c + 1 < NCH);
        const uint32_t sA = baseA + (uint32_t)(s * stageH * 2);
        const uint32_t sW = baseW + (uint32_t)(s * stageH * 2);
        __half* nA = stA + (s ^ 1) * stageH;
        __half* nW = stW + (s ^ 1) * stageH;

        if (more) load_frag(Ap + (c + 1) * BK, ua);

        {
            uint32_t a[2][4], b[4][4];
#pragma unroll
            for (int mt = 0; mt < 2; mt++)
                ldsm_x4(sA + offA[mt], a[mt][0], a[mt][1], a[mt][2], a[mt][3]);
#pragma unroll
            for (int nb = 0; nb < 4; nb++)
                ldsm_x4(sW + offB[nb], b[nb][0], b[nb][1], b[nb][2], b[nb][3]);
#pragma unroll
            for (int mt = 0; mt < 2; mt++)
#pragma unroll
                for (int nb = 0; nb < 4; nb++) {
                    mma16816(acc[mt][2 * nb],     a[mt], b[nb][0], b[nb][1]);
                    mma16816(acc[mt][2 * nb + 1], a[mt], b[nb][2], b[nb][3]);
                }
        }

        if (more) { st16(nA, ua); load_frag(Wp + (c + 1) * BK, uw); }

        {
            uint32_t a[2][4], b[4][4];
#pragma unroll
            for (int mt = 0; mt < 2; mt++)
                ldsm_x4(sA + offA[mt] + 32, a[mt][0], a[mt][1], a[mt][2], a[mt][3]);
#pragma unroll
            for (int nb = 0; nb < 4; nb++)
                ldsm_x4(sW + offB[nb] + 32, b[nb][0], b[nb][1], b[nb][2], b[nb][3]);
#pragma unroll
            for (int mt = 0; mt < 2; mt++)
#pragma unroll
                for (int nb = 0; nb < 4; nb++) {
                    mma16816(acc[mt][2 * nb],     a[mt], b[nb][0], b[nb][1]);
                    mma16816(acc[mt][2 * nb + 1], a[mt], b[nb][2], b[nb][3]);
                }
        }

        if (more) st16(nW, uw);
        __syncthreads();
    }

    // ---- epilogue (+RoPE); even/odd col pair lives inside one thread ----
    const int qr = lid >> 2;
    const int qc = (lid & 3) * 2;

    float inv[8];
    if (ROPE) {
#pragma unroll
        for (int nt = 0; nt < 8; nt++) {
            const int d = wn * 64 + nt * 8 + qc;
            inv[nt] = powf(10000.f, -(float)d * (1.f / 128.f));
        }
    }

#pragma unroll
    for (int mt = 0; mt < 2; mt++) {
#pragma unroll
        for (int h = 0; h < 2; h++) {
            const int m = m0 + wm * 32 + mt * 16 + qr + h * 8;
            const float pos = (float)(m & (SEQ - 1));
#pragma unroll
            for (int nt = 0; nt < 8; nt++) {
                float e = acc[mt][nt][2 * h + 0];
                float o = acc[mt][nt][2 * h + 1];
                if (ROPE) {
                    float sn, cs;
                    sincosf(pos * inv[nt], &sn, &cs);
                    const float e2 = e * cs - o * sn;
                    o = e * sn + o * cs;
                    e = e2;
                }
                const int col = n0 + wn * 64 + nt * 8 + qc;
                if (HOUT) {
                    __half2 hv = __floats2half2_rn(e, o);
                    *reinterpret_cast<__half2*>(
                        (__half*)Cv + (size_t)m * DMODEL + col) = hv;
                } else {
                    *(float2*)((float*)Cv + (size_t)m * DMODEL + col) =
                        make_float2(e, o);
                }
            }
        }
    }
}

// ---------------------------------------------------------------------------
// HMMA flash attention (causal). Grid (SEQ/128, NHEADS, BATCH), 256 threads.
// 8 warps x 16 query rows; KV tiles of 64. Q frags resident in registers.
// S-frag -> P A-frag register identity (no P through smem). fp32 softmax.
// ---------------------------------------------------------------------------
#define AT_STRIDE 136    // halves per smem row (128 + 8) -> ldmatrix conflict-free

__global__ __launch_bounds__(256)
void attn_hmma(const __half* __restrict__ Q, const __half* __restrict__ K,
               const __half* __restrict__ V, __half* __restrict__ O)
{
    __shared__ __align__(16) __half sKV[128 * AT_STRIDE];   // Q stage, then K|V

    const int tid = threadIdx.x;
    const int wid = tid >> 5;
    const int lid = tid & 31;
    const int qt  = blockIdx.x;
    const int h   = blockIdx.y;
    const int b   = blockIdx.z;
    const int q0  = qt * 128;

    const size_t base = (size_t)b * SEQ * DMODEL + (size_t)h * DHEAD;
    const uint32_t sb = smem_u32(sKV);
    const float K1 = 0.08838834764831845f * 1.4426950408889634f;  // scale*log2(e)

    // ---- stage Q tile (128x128 half), pull A-frags to registers ----
    for (int i = tid; i < 128 * 16; i += 256) {
        const int r  = i >> 4;
        const int db = i & 15;
        *(uint4*)&sKV[r * AT_STRIDE + db * 8] =
            *(const uint4*)&Q[base + (size_t)(q0 + r) * DMODEL + db * 8];
    }
    __syncthreads();

    uint32_t qf[8][4];
    {
        const int arow = wid * 16 + (lid & 15);
        const int acol = (lid >> 4) << 3;
#pragma unroll
        for (int kst = 0; kst < 8; kst++)
            ldsm_x4(sb + (uint32_t)(((arow) * AT_STRIDE + kst * 16 + acol) * 2),
                    qf[kst][0], qf[kst][1], qf[kst][2], qf[kst][3]);
    }

    float acc[16][4];
#pragma unroll
    for (int nt = 0; nt < 16; nt++)
#pragma unroll
        for (int i = 0; i < 4; i++) acc[nt][i] = 0.f;
    float mrow0 = -1e30f, mrow1 = -1e30f, lrow0 = 0.f, lrow1 = 0.f;

    const int r0  = lid >> 2;          // 0..7
    const int qcl = (lid & 3) * 2;
    const int wrow_min = q0 + wid * 16;
    const int ntiles = 2 * qt + 2;

    for (int kt = 0; kt < ntiles; kt++) {
        const int kv0 = kt * 64;
        __syncthreads();
        // ---- load K (rows 0-63) and V (rows 64-127 region) tiles ----
        for (int i = tid; i < 64 * 16; i += 256) {
            const int c  = i >> 4;
            const int db = i & 15;
            const size_t src = base + (size_t)(kv0 + c) * DMODEL + db * 8;
            *(uint4*)&sKV[c * AT_STRIDE + db * 8]               = *(const uint4*)&K[src];
            *(uint4*)&sKV[(64 + c) * AT_STRIDE + db * 8]        = *(const uint4*)&V[src];
        }
        __syncthreads();

        const bool active = (kv0 <= wrow_min + 15);
        if (!active) continue;

        // ---- S = Q K^T (16x64 per warp) ----
        float sc[8][4];
#pragma unroll
        for (int nt = 0; nt < 8; nt++)
#pragma unroll
            for (int i = 0; i < 4; i++) sc[nt][i] = 0.f;

#pragma unroll
        for (int kst = 0; kst < 8; kst++) {
#pragma unroll
            for (int np = 0; np < 4; np++) {
                uint32_t b0, b1, b2, b3;
                const int krow = np * 16 + (lid & 7) + ((lid & 16) ? 8 : 0);
                const int kcol = kst * 16 + ((lid & 8) ? 8 : 0);
                ldsm_x4(sb + (uint32_t)((krow * AT_STRIDE + kcol) * 2), b0, b1, b2, b3);
                mma16816(sc[2 * np],     qf[kst], b0, b1);
                mma16816(sc[2 * np + 1], qf[kst], b2, b3);
            }
        }

        // ---- causal mask (only near-diagonal warp-tiles) ----
        const int row0 = wrow_min + r0;
        const int row1 = row0 + 8;
        if (kv0 + 63 > wrow_min) {
#pragma unroll
            for (int nt = 0; nt < 8; nt++) {
                const int col = kv0 + nt * 8 + qcl;
                if (col     > row0) sc[nt][0] = -1e30f;
                if (col + 1 > row0) sc[nt][1] = -1e30f;
                if (col     > row1) sc[nt][2] = -1e30f;
                if (col + 1 > row1) sc[nt][3] = -1e30f;
            }
        }

        // ---- online softmax (quad reduce over lanes sharing a row) ----
        float m0 = -1e30f, m1 = -1e30f;
#pragma unroll
        for (int nt = 0; nt < 8; nt++) {
            m0 = fmaxf(m0, fmaxf(sc[nt][0], sc[nt][1]));
            m1 = fmaxf(m1, fmaxf(sc[nt][2], sc[nt][3]));
        }
        m0 = fmaxf(m0, __shfl_xor_sync(0xffffffffu, m0, 1));
        m0 = fmaxf(m0, __shfl_xor_sync(0xffffffffu, m0, 2));
        m1 = fmaxf(m1, __shfl_xor_sync(0xffffffffu, m1, 1));
        m1 = fmaxf(m1, __shfl_xor_sync(0xffffffffu, m1, 2));

        const float mn0 = fmaxf(mrow0, m0);
        const float mn1 = fmaxf(mrow1, m1);
        const float al0 = fast_exp2((mrow0 - mn0) * K1);
        const float al1 = fast_exp2((mrow1 - mn1) * K1);
        mrow0 = mn0; mrow1 = mn1;
        const float nk0 = mn0 * K1;
        const float nk1 = mn1 * K1;

        float rs0 = 0.f, rs1 = 0.f;
        uint32_t ph[8][2];
#pragma unroll
        for (int nt = 0; nt < 8; nt++) {
            const float p0 = fast_exp2(fmaf(sc[nt][0], K1, -nk0));
            const float p1 = fast_exp2(fmaf(sc[nt][1], K1, -nk0));
            const float p2 = fast_exp2(fmaf(sc[nt][2], K1, -nk1));
            const float p3 = fast_exp2(fmaf(sc[nt][3], K1, -nk1));
            rs0 += p0 + p1;
            rs1 += p2 + p3;
            __half2 h0 = __floats2half2_rn(p0, p1);
            __half2 h1 = __floats2half2_rn(p2, p3);
            ph[nt][0] = *reinterpret_cast<uint32_t*>(&h0);
            ph[nt][1] = *reinterpret_cast<uint32_t*>(&h1);
        }
        rs0 += __shfl_xor_sync(0xffffffffu, rs0, 1);
        rs0 += __shfl_xor_sync(0xffffffffu, rs0, 2);
        rs1 += __shfl_xor_sync(0xffffffffu, rs1, 1);
        rs1 += __shfl_xor_sync(0xffffffffu, rs1, 2);
        lrow0 = lrow0 * al0 + rs0;
        lrow1 = lrow1 * al1 + rs1;

#pragma unroll
        for (int nt = 0; nt < 16; nt++) {
            acc[nt][0] *= al0; acc[nt][1] *= al0;
            acc[nt][2] *= al1; acc[nt][3] *= al1;
        }

        // ---- O += P V (P A-frags straight from S fragments) ----
#pragma unroll
        for (int kc = 0; kc < 4; kc++) {
            uint32_t a[4] = { ph[2 * kc][0], ph[2 * kc][1],
                              ph[2 * kc + 1][0], ph[2 * kc + 1][1] };
#pragma unroll
            for (int dp = 0; dp < 8; dp++) {
                uint32_t v0, v1, v2, v3;
                const int vrow = 64 + kc * 16 + (lid & 7) + ((lid & 8) ? 8 : 0);
                const int vcol = dp * 16 + ((lid & 16) ? 8 : 0);
                ldsm_x4_t(sb + (uint32_t)((vrow * AT_STRIDE + vcol) * 2), v0, v1, v2, v3);
                mma16816(acc[2 * dp],     a, v0, v1);
                mma16816(acc[2 * dp + 1], a, v2, v3);
            }
        }
    }

    // ---- normalize + fp16 store ----
    const float inv0 = 1.f / lrow0;
    const float inv1 = 1.f / lrow1;
    const int gr0 = q0 + wid * 16 + r0;
    __half* o0 = O + base + (size_t)gr0 * DMODEL;
    __half* o1 = O + base + (size_t)(gr0 + 8) * DMODEL;
#pragma unroll
    for (int nt = 0; nt < 16; nt++) {
        const int col = nt * 8 + qcl;
        __half2 h0 = __floats2half2_rn(acc[nt][0] * inv0, acc[nt][1] * inv0);
        __half2 h1 = __floats2half2_rn(acc[nt][2] * inv1, acc[nt][3] * inv1);
        *reinterpret_cast<__half2*>(o0 + col) = h0;
        *reinterpret_cast<__half2*>(o1 + col) = h1;
    }
}

// ---------------------------------------------------------------------------
// Launch
// ---------------------------------------------------------------------------
extern "C" void kernel_launch(void* const* d_in, const int* in_sizes, int n_in,
                              void* d_out, int out_size)
{
    const float* x  = (const float*)d_in[0];
    const float* wq = (const float*)d_in[1];
    const float* wk = (const float*)d_in[2];
    const float* wv = (const float*)d_in[3];
    const float* wo = (const float*)d_in[4];
    float* out = (float*)d_out;

    __half *qh, *kh, *vh, *aoh;
    cudaGetSymbolAddress((void**)&qh,  g_qh);
    cudaGetSymbolAddress((void**)&kh,  g_kh);
    cudaGetSymbolAddress((void**)&vh,  g_vh);
    cudaGetSymbolAddress((void**)&aoh, g_aoh);

    dim3 gg(DMODEL / 128, MTOT / 128);   // (16, 32)

    gemm_hmma<true,  true,  float><<<gg, 256>>>(x, wq, qh);   // Q proj + RoPE -> fp16
    gemm_hmma<true,  true,  float><<<gg, 256>>>(x, wk, kh);   // K proj + RoPE -> fp16
    gemm_hmma<false, true,  float><<<gg, 256>>>(x, wv, vh);   // V proj -> fp16

    attn_hmma<<<dim3(SEQ / 128, NHEADS, BATCH), 256>>>(qh, kh, vh, aoh);

    gemm_hmma<false, false, __half><<<gg, 256>>>(aoh, wo, out);  // out proj (fp16 A)
}

// round 13
// speedup vs baseline: 6.0055x; 1.6406x over previous
#include <cuda_runtime.h>
#include <cuda_fp16.h>
#include <math.h>
#include <stdint.h>

#define BATCH   2
#define SEQ     2048
#define DMODEL  2048
#define NHEADS  16
#define DHEAD   128
#define MTOT    (BATCH * SEQ)   // 4096

// ---------------------------------------------------------------------------
// Scratch buffers (allocation-free rule: __device__ globals) — fp16 dataflow
// ---------------------------------------------------------------------------
__device__ __half g_xh [(size_t)MTOT * DMODEL];
__device__ __half g_wqh[(size_t)DMODEL * DMODEL];
__device__ __half g_wkh[(size_t)DMODEL * DMODEL];
__device__ __half g_wvh[(size_t)DMODEL * DMODEL];
__device__ __half g_woh[(size_t)DMODEL * DMODEL];
__device__ __half g_qh [(size_t)MTOT * DMODEL];
__device__ __half g_kh [(size_t)MTOT * DMODEL];
__device__ __half g_vh [(size_t)MTOT * DMODEL];
__device__ __half g_aoh[(size_t)MTOT * DMODEL];

// ---------------------------------------------------------------------------
// Helpers (baseline-family PTX only: ldmatrix sm_75+, mma/cp.async sm_80+)
// ---------------------------------------------------------------------------
__device__ __forceinline__ uint32_t smem_u32(const void* p) {
    uint32_t a;
    asm("{ .reg .u64 t; cvta.to.shared.u64 t, %1; cvt.u32.u64 %0, t; }"
        : "=r"(a) : "l"(p));
    return a;
}

__device__ __forceinline__ void ldsm_x4(uint32_t addr, uint32_t& r0, uint32_t& r1,
                                        uint32_t& r2, uint32_t& r3) {
    asm volatile("ldmatrix.sync.aligned.m8n8.x4.shared.b16 {%0,%1,%2,%3}, [%4];"
                 : "=r"(r0), "=r"(r1), "=r"(r2), "=r"(r3) : "r"(addr));
}

__device__ __forceinline__ void ldsm_x4_t(uint32_t addr, uint32_t& r0, uint32_t& r1,
                                          uint32_t& r2, uint32_t& r3) {
    asm volatile("ldmatrix.sync.aligned.m8n8.x4.trans.shared.b16 {%0,%1,%2,%3}, [%4];"
                 : "=r"(r0), "=r"(r1), "=r"(r2), "=r"(r3) : "r"(addr));
}

__device__ __forceinline__ void mma16816(float* d, const uint32_t* a,
                                         uint32_t b0, uint32_t b1) {
    asm volatile("mma.sync.aligned.m16n8k16.row.col.f32.f16.f16.f32 "
                 "{%0,%1,%2,%3}, {%4,%5,%6,%7}, {%8,%9}, {%0,%1,%2,%3};"
                 : "+f"(d[0]), "+f"(d[1]), "+f"(d[2]), "+f"(d[3])
                 : "r"(a[0]), "r"(a[1]), "r"(a[2]), "r"(a[3]), "r"(b0), "r"(b1));
}

__device__ __forceinline__ float fast_exp2(float x) {
    float y;
    asm("ex2.approx.ftz.f32 %0, %1;" : "=f"(y) : "f"(x));
    return y;
}

#define CP_ASYNC16(smem, gptr) \
    asm volatile("cp.async.cg.shared.global [%0], [%1], 16;" \
                 :: "r"(smem), "l"(gptr) : "memory")
#define CP_COMMIT()  asm volatile("cp.async.commit_group;" ::: "memory")
#define CP_WAIT(n)   asm volatile("cp.async.wait_group %0;" :: "n"(n) : "memory")

// ---------------------------------------------------------------------------
// fp32 -> fp16 converter (grid-stride, 8 elems/thread)
// ---------------------------------------------------------------------------
__global__ __launch_bounds__(256)
void cvt_f16(const float* __restrict__ src, __half* __restrict__ dst, int n)
{
    const int i = (blockIdx.x * 256 + threadIdx.x) * 8;
    if (i >= n) return;
    float4 v0 = *(const float4*)(src + i);
    float4 v1 = *(const float4*)(src + i + 4);
    __half2 h0 = __floats2half2_rn(v0.x, v0.y);
    __half2 h1 = __floats2half2_rn(v0.z, v0.w);
    __half2 h2 = __floats2half2_rn(v1.x, v1.y);
    __half2 h3 = __floats2half2_rn(v1.z, v1.w);
    *(uint4*)(dst + i) = make_uint4(*(uint32_t*)&h0, *(uint32_t*)&h1,
                                    *(uint32_t*)&h2, *(uint32_t*)&h3);
}

// ---------------------------------------------------------------------------
// HMMA fp16 GEMM:  C[m][n] = sum_k A[m][k] * W[n][k]   (both K-major, NT)
// 128x128 CTA tile, 8 warps (4x2 -> warp tile 32x64), BK=32.
// cp.async 4-stage pipeline, pure fp16 operands. Optional fused RoPE.
// ---------------------------------------------------------------------------
#define BK       32
#define NCH      (DMODEL / BK)    // 64
#define LDS_ROW  40               // halves per smem row (32 + 8 pad)
#define STG_HALF (128 * LDS_ROW)  // halves per operand per stage
#define STG_A_B  (STG_HALF * 2)   // 10240 bytes
#define STG_B    (2 * STG_A_B)    // 20480 bytes (A + W)
#define NSTAGE   4
#define GEMM_SMEM (NSTAGE * STG_B)   // 81920 bytes

template<bool ROPE, bool HOUT>
__global__ __launch_bounds__(256, 2)
void gemm_hmma(const __half* __restrict__ A, const __half* __restrict__ W,
               void* __restrict__ Cv)
{
    extern __shared__ char dsm[];
    const uint32_t sb = smem_u32(dsm);

    const int tid = threadIdx.x;
    const int wid = tid >> 5;
    const int lid = tid & 31;
    const int wm  = wid >> 1;
    const int wn  = wid & 1;
    const int m0  = blockIdx.y * 128;
    const int n0  = blockIdx.x * 128;

    // per-thread cp.async slice: row r, 16 halves at side*16 (2x16B)
    const int r    = tid >> 1;
    const int side = tid & 1;
    const __half* Ap = A + (size_t)(m0 + r) * DMODEL + side * 16;
    const __half* Wp = W + (size_t)(n0 + r) * DMODEL + side * 16;
    const uint32_t dA = sb + (uint32_t)(r * (LDS_ROW * 2) + side * 32);
    const uint32_t dW = dA + STG_A_B;

    auto issue = [&](int c) {
        const uint32_t so = (uint32_t)((c & (NSTAGE - 1)) * STG_B);
        const __half* ga = Ap + c * BK;
        const __half* gw = Wp + c * BK;
        CP_ASYNC16(dA + so,      ga);
        CP_ASYNC16(dA + so + 16, ga + 8);
        CP_ASYNC16(dW + so,      gw);
        CP_ASYNC16(dW + so + 16, gw + 8);
        CP_COMMIT();
    };

    // ldmatrix lane offsets (bytes within stage); k-step 1 adds 32B
    uint32_t offA[2], offB[4];
#pragma unroll
    for (int mt = 0; mt < 2; mt++) {
        const int row = wm * 32 + mt * 16 + (lid & 15);
        const int col = (lid >> 4) << 3;
        offA[mt] = (uint32_t)((row * LDS_ROW + col) * 2);
    }
#pragma unroll
    for (int nb = 0; nb < 4; nb++) {
        const int row = wn * 64 + nb * 16 + (lid & 7) + ((lid & 16) ? 8 : 0);
        const int col = (lid & 8) ? 8 : 0;
        offB[nb] = (uint32_t)((row * LDS_ROW + col) * 2 + STG_A_B);
    }

    float acc[2][8][4];
#pragma unroll
    for (int mt = 0; mt < 2; mt++)
#pragma unroll
        for (int nt = 0; nt < 8; nt++)
#pragma unroll
            for (int i = 0; i < 4; i++) acc[mt][nt][i] = 0.f;

    issue(0); issue(1); issue(2);

    for (int c = 0; c < NCH; c++) {
        CP_WAIT(2);
        __syncthreads();
        if (c + 3 < NCH) issue(c + 3);

        const uint32_t st = sb + (uint32_t)((c & (NSTAGE - 1)) * STG_B);
#pragma unroll
        for (int ks = 0; ks < 2; ks++) {
            const uint32_t kso = (uint32_t)(ks * 32);
            uint32_t a[2][4], b[4][4];
#pragma unroll
            for (int mt = 0; mt < 2; mt++)
                ldsm_x4(st + offA[mt] + kso, a[mt][0], a[mt][1], a[mt][2], a[mt][3]);
#pragma unroll
            for (int nb = 0; nb < 4; nb++)
                ldsm_x4(st + offB[nb] + kso, b[nb][0], b[nb][1], b[nb][2], b[nb][3]);
#pragma unroll
            for (int mt = 0; mt < 2; mt++)
#pragma unroll
                for (int nb = 0; nb < 4; nb++) {
                    mma16816(acc[mt][2 * nb],     a[mt], b[nb][0], b[nb][1]);
                    mma16816(acc[mt][2 * nb + 1], a[mt], b[nb][2], b[nb][3]);
                }
        }
    }

    // ---- epilogue (+RoPE); even/odd col pair lives inside one thread ----
    const int qr = lid >> 2;
    const int qc = (lid & 3) * 2;

    float inv[8];
    if (ROPE) {
#pragma unroll
        for (int nt = 0; nt < 8; nt++) {
            const int d = wn * 64 + nt * 8 + qc;
            inv[nt] = powf(10000.f, -(float)d * (1.f / 128.f));
        }
    }

#pragma unroll
    for (int mt = 0; mt < 2; mt++) {
#pragma unroll
        for (int h = 0; h < 2; h++) {
            const int m = m0 + wm * 32 + mt * 16 + qr + h * 8;
            const float pos = (float)(m & (SEQ - 1));
#pragma unroll
            for (int nt = 0; nt < 8; nt++) {
                float e = acc[mt][nt][2 * h + 0];
                float o = acc[mt][nt][2 * h + 1];
                if (ROPE) {
                    float sn, cs;
                    sincosf(pos * inv[nt], &sn, &cs);
                    const float e2 = e * cs - o * sn;
                    o = e * sn + o * cs;
                    e = e2;
                }
                const int col = n0 + wn * 64 + nt * 8 + qc;
                if (HOUT) {
                    __half2 hv = __floats2half2_rn(e, o);
                    *reinterpret_cast<__half2*>(
                        (__half*)Cv + (size_t)m * DMODEL + col) = hv;
                } else {
                    *(float2*)((float*)Cv + (size_t)m * DMODEL + col) =
                        make_float2(e, o);
                }
            }
        }
    }
}

// ---------------------------------------------------------------------------
// HMMA flash attention (causal). Grid (SEQ/128, NHEADS, BATCH), 256 threads.
// 8 warps x 16 query rows; KV tiles of 64, double-buffered via cp.async.
// S-frag -> P A-frag register identity (no P through smem). fp32 softmax.
// ---------------------------------------------------------------------------
#define AT_STRIDE  136                      // halves per row (128 + 8)
#define AT_ROW_B   (AT_STRIDE * 2)          // 272 bytes
#define AT_STAGE_B (128 * AT_ROW_B)         // 34816 bytes (K rows 0-63, V 64-127)
#define ATTN_SMEM  (2 * AT_STAGE_B)         // 69632 bytes

__global__ __launch_bounds__(256)
void attn_hmma(const __half* __restrict__ Q, const __half* __restrict__ K,
               const __half* __restrict__ V, __half* __restrict__ O)
{
    extern __shared__ char dsm[];
    __half* sKV = (__half*)dsm;
    const uint32_t sb = smem_u32(dsm);

    const int tid = threadIdx.x;
    const int wid = tid >> 5;
    const int lid = tid & 31;
    const int qt  = blockIdx.x;
    const int h   = blockIdx.y;
    const int b   = blockIdx.z;
    const int q0  = qt * 128;

    const size_t base = (size_t)b * SEQ * DMODEL + (size_t)h * DHEAD;
    const float K1 = 0.08838834764831845f * 1.4426950408889634f;  // scale*log2(e)

    // ---- stage Q tile (128x128 half) in stage 0, pull A-frags ----
    for (int i = tid; i < 128 * 16; i += 256) {
        const int rr = i >> 4;
        const int db = i & 15;
        *(uint4*)&sKV[rr * AT_STRIDE + db * 8] =
            *(const uint4*)&Q[base + (size_t)(q0 + rr) * DMODEL + db * 8];
    }
    __syncthreads();

    uint32_t qf[8][4];
    {
        const int arow = wid * 16 + (lid & 15);
        const int acol = (lid >> 4) << 3;
#pragma unroll
        for (int kst = 0; kst < 8; kst++)
            ldsm_x4(sb + (uint32_t)((arow * AT_STRIDE + kst * 16 + acol) * 2),
                    qf[kst][0], qf[kst][1], qf[kst][2], qf[kst][3]);
    }
    __syncthreads();   // all Q frags read before stage 0 is overwritten by KV

    auto issueKV = [&](int kt, int s) {
        const uint32_t stg = sb + (uint32_t)(s * AT_STAGE_B);
        const int kv0 = kt * 64;
#pragma unroll
        for (int j = 0; j < 4; j++) {
            const int idx = tid + j * 256;    // 0..1023
            const int c   = idx >> 4;         // kv row 0..63
            const int db  = idx & 15;         // 16B chunk
            const size_t src = base + (size_t)(kv0 + c) * DMODEL + db * 8;
            CP_ASYNC16(stg + (uint32_t)(c * AT_ROW_B + db * 16),        &K[src]);
            CP_ASYNC16(stg + (uint32_t)((64 + c) * AT_ROW_B + db * 16), &V[src]);
        }
        CP_COMMIT();
    };

    float acc[16][4];
#pragma unroll
    for (int nt = 0; nt < 16; nt++)
#pragma unroll
        for (int i = 0; i < 4; i++) acc[nt][i] = 0.f;
    float mrow0 = -1e30f, mrow1 = -1e30f, lrow0 = 0.f, lrow1 = 0.f;

    const int r0  = lid >> 2;
    const int qcl = (lid & 3) * 2;
    const int wrow_min = q0 + wid * 16;
    const int ntiles = 2 * qt + 2;

    issueKV(0, 0);

    for (int kt = 0; kt < ntiles; kt++) {
        const int s   = kt & 1;
        const int kv0 = kt * 64;

        if (kt + 1 < ntiles) { issueKV(kt + 1, s ^ 1); CP_WAIT(1); }
        else                 { CP_WAIT(0); }
        __syncthreads();

        if (kv0 <= wrow_min + 15) {
            const uint32_t stg = sb + (uint32_t)(s * AT_STAGE_B);

            // ---- S = Q K^T (16x64 per warp) ----
            float sc[8][4];
#pragma unroll
            for (int nt = 0; nt < 8; nt++)
#pragma unroll
                for (int i = 0; i < 4; i++) sc[nt][i] = 0.f;

#pragma unroll
            for (int kst = 0; kst < 8; kst++) {
#pragma unroll
                for (int np = 0; np < 4; np++) {
                    uint32_t b0, b1, b2, b3;
                    const int krow = np * 16 + (lid & 7) + ((lid & 16) ? 8 : 0);
                    const int kcol = kst * 16 + ((lid & 8) ? 8 : 0);
                    ldsm_x4(stg + (uint32_t)((krow * AT_STRIDE + kcol) * 2),
                            b0, b1, b2, b3);
                    mma16816(sc[2 * np],     qf[kst], b0, b1);
                    mma16816(sc[2 * np + 1], qf[kst], b2, b3);
                }
            }

            // ---- causal mask (only near-diagonal warp-tiles) ----
            const int row0 = wrow_min + r0;
            const int row1 = row0 + 8;
            if (kv0 + 63 > wrow_min) {
#pragma unroll
                for (int nt = 0; nt < 8; nt++) {
                    const int col = kv0 + nt * 8 + qcl;
                    if (col     > row0) sc[nt][0] = -1e30f;
                    if (col + 1 > row0) sc[nt][1] = -1e30f;
                    if (col     > row1) sc[nt][2] = -1e30f;
                    if (col + 1 > row1) sc[nt][3] = -1e30f;
                }
            }

            // ---- online softmax (quad reduce over lanes sharing a row) ----
            float m0 = -1e30f, m1 = -1e30f;
#pragma unroll
            for (int nt = 0; nt < 8; nt++) {
                m0 = fmaxf(m0, fmaxf(sc[nt][0], sc[nt][1]));
                m1 = fmaxf(m1, fmaxf(sc[nt][2], sc[nt][3]));
            }
            m0 = fmaxf(m0, __shfl_xor_sync(0xffffffffu, m0, 1));
            m0 = fmaxf(m0, __shfl_xor_sync(0xffffffffu, m0, 2));
            m1 = fmaxf(m1, __shfl_xor_sync(0xffffffffu, m1, 1));
            m1 = fmaxf(m1, __shfl_xor_sync(0xffffffffu, m1, 2));

            const float mn0 = fmaxf(mrow0, m0);
            const float mn1 = fmaxf(mrow1, m1);
            const float al0 = fast_exp2((mrow0 - mn0) * K1);
            const float al1 = fast_exp2((mrow1 - mn1) * K1);
            mrow0 = mn0; mrow1 = mn1;
            const float nk0 = mn0 * K1;
            const float nk1 = mn1 * K1;

            float rs0 = 0.f, rs1 = 0.f;
            uint32_t ph[8][2];
#pragma unroll
            for (int nt = 0; nt < 8; nt++) {
                const float p0 = fast_exp2(fmaf(sc[nt][0], K1, -nk0));
                const float p1 = fast_exp2(fmaf(sc[nt][1], K1, -nk0));
                const float p2 = fast_exp2(fmaf(sc[nt][2], K1, -nk1));
                const float p3 = fast_exp2(fmaf(sc[nt][3], K1, -nk1));
                rs0 += p0 + p1;
                rs1 += p2 + p3;
                __half2 h0 = __floats2half2_rn(p0, p1);
                __half2 h1 = __floats2half2_rn(p2, p3);
                ph[nt][0] = *reinterpret_cast<uint32_t*>(&h0);
                ph[nt][1] = *reinterpret_cast<uint32_t*>(&h1);
            }
            rs0 += __shfl_xor_sync(0xffffffffu, rs0, 1);
            rs0 += __shfl_xor_sync(0xffffffffu, rs0, 2);
            rs1 += __shfl_xor_sync(0xffffffffu, rs1, 1);
            rs1 += __shfl_xor_sync(0xffffffffu, rs1, 2);
            lrow0 = lrow0 * al0 + rs0;
            lrow1 = lrow1 * al1 + rs1;

#pragma unroll
            for (int nt = 0; nt < 16; nt++) {
                acc[nt][0] *= al0; acc[nt][1] *= al0;
                acc[nt][2] *= al1; acc[nt][3] *= al1;
            }

            // ---- O += P V (P A-frags straight from S fragments) ----
#pragma unroll
            for (int kc = 0; kc < 4; kc++) {
                uint32_t a[4] = { ph[2 * kc][0], ph[2 * kc][1],
                                  ph[2 * kc + 1][0], ph[2 * kc + 1][1] };
#pragma unroll
                for (int dp = 0; dp < 8; dp++) {
                    uint32_t v0, v1, v2, v3;
                    const int vrow = 64 + kc * 16 + (lid & 7) + ((lid & 8) ? 8 : 0);
                    const int vcol = dp * 16 + ((lid & 16) ? 8 : 0);
                    ldsm_x4_t(stg + (uint32_t)((vrow * AT_STRIDE + vcol) * 2),
                              v0, v1, v2, v3);
                    mma16816(acc[2 * dp],     a, v0, v1);
                    mma16816(acc[2 * dp + 1], a, v2, v3);
                }
            }
        }
        __syncthreads();   // all warps done with stage s before it is rewritten
    }

    // ---- normalize + fp16 store ----
    const float inv0 = 1.f / lrow0;
    const float inv1 = 1.f / lrow1;
    const int gr0 = q0 + wid * 16 + r0;
    __half* o0 = O + base + (size_t)gr0 * DMODEL;
    __half* o1 = O + base + (size_t)(gr0 + 8) * DMODEL;
#pragma unroll
    for (int nt = 0; nt < 16; nt++) {
        const int col = nt * 8 + qcl;
        __half2 h0 = __floats2half2_rn(acc[nt][0] * inv0, acc[nt][1] * inv0);
        __half2 h1 = __floats2half2_rn(acc[nt][2] * inv1, acc[nt][3] * inv1);
        *reinterpret_cast<__half2*>(o0 + col) = h0;
        *reinterpret_cast<__half2*>(o1 + col) = h1;
    }
}

// ---------------------------------------------------------------------------
// Launch
// ---------------------------------------------------------------------------
extern "C" void kernel_launch(void* const* d_in, const int* in_sizes, int n_in,
                              void* d_out, int out_size)
{
    const float* x  = (const float*)d_in[0];
    const float* wq = (const float*)d_in[1];
    const float* wk = (const float*)d_in[2];
    const float* wv = (const float*)d_in[3];
    const float* wo = (const float*)d_in[4];
    float* out = (float*)d_out;

    __half *xh, *wqh, *wkh, *wvh, *woh, *qh, *kh, *vh, *aoh;
    cudaGetSymbolAddress((void**)&xh,  g_xh);
    cudaGetSymbolAddress((void**)&wqh, g_wqh);
    cudaGetSymbolAddress((void**)&wkh, g_wkh);
    cudaGetSymbolAddress((void**)&wvh, g_wvh);
    cudaGetSymbolAddress((void**)&woh, g_woh);
    cudaGetSymbolAddress((void**)&qh,  g_qh);
    cudaGetSymbolAddress((void**)&kh,  g_kh);
    cudaGetSymbolAddress((void**)&vh,  g_vh);
    cudaGetSymbolAddress((void**)&aoh, g_aoh);

    cudaFuncSetAttribute(gemm_hmma<true,  true>,
                         cudaFuncAttributeMaxDynamicSharedMemorySize, GEMM_SMEM);
    cudaFuncSetAttribute(gemm_hmma<false, true>,
                         cudaFuncAttributeMaxDynamicSharedMemorySize, GEMM_SMEM);
    cudaFuncSetAttribute(gemm_hmma<false, false>,
                         cudaFuncAttributeMaxDynamicSharedMemorySize, GEMM_SMEM);
    cudaFuncSetAttribute(attn_hmma,
                         cudaFuncAttributeMaxDynamicSharedMemorySize, ATTN_SMEM);

    // ---- one-time fp32 -> fp16 conversions ----
    const int nx = MTOT * DMODEL;      // 8.4M
    const int nw = DMODEL * DMODEL;    // 4.2M
    cvt_f16<<<nx / 2048, 256>>>(x,  xh,  nx);
    cvt_f16<<<nw / 2048, 256>>>(wq, wqh, nw);
    cvt_f16<<<nw / 2048, 256>>>(wk, wkh, nw);
    cvt_f16<<<nw / 2048, 256>>>(wv, wvh, nw);
    cvt_f16<<<nw / 2048, 256>>>(wo, woh, nw);

    dim3 gg(DMODEL / 128, MTOT / 128);   // (16, 32)

    gemm_hmma<true,  true ><<<gg, 256, GEMM_SMEM>>>(xh, wqh, qh);   // Q + RoPE
    gemm_hmma<true,  true ><<<gg, 256, GEMM_SMEM>>>(xh, wkh, kh);   // K + RoPE
    gemm_hmma<false, true ><<<gg, 256, GEMM_SMEM>>>(xh, wvh, vh);   // V

    attn_hmma<<<dim3(SEQ / 128, NHEADS, BATCH), 256, ATTN_SMEM>>>(qh, kh, vh, aoh);

    gemm_hmma<false, false><<<gg, 256, GEMM_SMEM>>>(aoh, woh, out); // out proj
}

// round 14
// speedup vs baseline: 6.4363x; 1.0717x over previous
#include <cuda_runtime.h>
#include <cuda_fp16.h>
#include <math.h>
#include <stdint.h>

#define BATCH   2
#define SEQ     2048
#define DMODEL  2048
#define NHEADS  16
#define DHEAD   128
#define MTOT    (BATCH * SEQ)   // 4096

// ---------------------------------------------------------------------------
// Scratch buffers (allocation-free rule: __device__ globals) — fp16 dataflow
// ---------------------------------------------------------------------------
__device__ __half g_xh [(size_t)MTOT * DMODEL];
__device__ __half g_wqh[(size_t)DMODEL * DMODEL];
__device__ __half g_wkh[(size_t)DMODEL * DMODEL];
__device__ __half g_wvh[(size_t)DMODEL * DMODEL];
__device__ __half g_woh[(size_t)DMODEL * DMODEL];
__device__ __half g_qh [(size_t)MTOT * DMODEL];
__device__ __half g_kh [(size_t)MTOT * DMODEL];
__device__ __half g_vh [(size_t)MTOT * DMODEL];
__device__ __half g_aoh[(size_t)MTOT * DMODEL];

// ---------------------------------------------------------------------------
// Helpers (baseline-family PTX only: ldmatrix sm_75+, mma/cp.async sm_80+)
// ---------------------------------------------------------------------------
__device__ __forceinline__ uint32_t smem_u32(const void* p) {
    uint32_t a;
    asm("{ .reg .u64 t; cvta.to.shared.u64 t, %1; cvt.u32.u64 %0, t; }"
        : "=r"(a) : "l"(p));
    return a;
}

__device__ __forceinline__ void ldsm_x4(uint32_t addr, uint32_t& r0, uint32_t& r1,
                                        uint32_t& r2, uint32_t& r3) {
    asm volatile("ldmatrix.sync.aligned.m8n8.x4.shared.b16 {%0,%1,%2,%3}, [%4];"
                 : "=r"(r0), "=r"(r1), "=r"(r2), "=r"(r3) : "r"(addr));
}

__device__ __forceinline__ void ldsm_x4_t(uint32_t addr, uint32_t& r0, uint32_t& r1,
                                          uint32_t& r2, uint32_t& r3) {
    asm volatile("ldmatrix.sync.aligned.m8n8.x4.trans.shared.b16 {%0,%1,%2,%3}, [%4];"
                 : "=r"(r0), "=r"(r1), "=r"(r2), "=r"(r3) : "r"(addr));
}

__device__ __forceinline__ void mma16816(float* d, const uint32_t* a,
                                         uint32_t b0, uint32_t b1) {
    asm volatile("mma.sync.aligned.m16n8k16.row.col.f32.f16.f16.f32 "
                 "{%0,%1,%2,%3}, {%4,%5,%6,%7}, {%8,%9}, {%0,%1,%2,%3};"
                 : "+f"(d[0]), "+f"(d[1]), "+f"(d[2]), "+f"(d[3])
                 : "r"(a[0]), "r"(a[1]), "r"(a[2]), "r"(a[3]), "r"(b0), "r"(b1));
}

__device__ __forceinline__ float fast_exp2(float x) {
    float y;
    asm("ex2.approx.ftz.f32 %0, %1;" : "=f"(y) : "f"(x));
    return y;
}

#define CP_ASYNC16(smem, gptr) \
    asm volatile("cp.async.cg.shared.global [%0], [%1], 16;" \
                 :: "r"(smem), "l"(gptr) : "memory")
#define CP_COMMIT()  asm volatile("cp.async.commit_group;" ::: "memory")
#define CP_WAIT(n)   asm volatile("cp.async.wait_group %0;" :: "n"(n) : "memory")

// ---------------------------------------------------------------------------
// Fused fp32 -> fp16 converter: one launch handles x + all 4 weights.
// blockIdx.y selects the tensor; grid.x sized for the largest (x).
// ---------------------------------------------------------------------------
__global__ __launch_bounds__(256)
void cvt_all(const float* __restrict__ x,  const float* __restrict__ wq,
             const float* __restrict__ wk, const float* __restrict__ wv,
             const float* __restrict__ wo,
             __half* __restrict__ xh,  __half* __restrict__ wqh,
             __half* __restrict__ wkh, __half* __restrict__ wvh,
             __half* __restrict__ woh)
{
    const float* src;
    __half* dst;
    int n;
    switch (blockIdx.y) {
        case 0:  src = x;  dst = xh;  n = MTOT * DMODEL;   break;
        case 1:  src = wq; dst = wqh; n = DMODEL * DMODEL; break;
        case 2:  src = wk; dst = wkh; n = DMODEL * DMODEL; break;
        case 3:  src = wv; dst = wvh; n = DMODEL * DMODEL; break;
        default: src = wo; dst = woh; n = DMODEL * DMODEL; break;
    }
    const int i = (blockIdx.x * 256 + threadIdx.x) * 8;
    if (i >= n) return;
    float4 v0 = *(const float4*)(src + i);
    float4 v1 = *(const float4*)(src + i + 4);
    __half2 h0 = __floats2half2_rn(v0.x, v0.y);
    __half2 h1 = __floats2half2_rn(v0.z, v0.w);
    __half2 h2 = __floats2half2_rn(v1.x, v1.y);
    __half2 h3 = __floats2half2_rn(v1.z, v1.w);
    *(uint4*)(dst + i) = make_uint4(*(uint32_t*)&h0, *(uint32_t*)&h1,
                                    *(uint32_t*)&h2, *(uint32_t*)&h3);
}

// ---------------------------------------------------------------------------
// HMMA fp16 GEMM core:  C[m][n] = sum_k A[m][k] * W[n][k]   (K-major NT)
// 128x128 CTA tile, 8 warps (4x2 -> warp tile 32x64), BK=32,
// cp.async 4-stage pipeline. Runtime 'rope' flag; HOUT template for dtype.
// ---------------------------------------------------------------------------
#define BK       32
#define NCH      (DMODEL / BK)    // 64
#define LDS_ROW  40               // halves per smem row (32 + 8 pad)
#define STG_HALF (128 * LDS_ROW)
#define STG_A_B  (STG_HALF * 2)   // 10240 bytes
#define STG_B    (2 * STG_A_B)    // 20480 bytes (A + W)
#define NSTAGE   4
#define GEMM_SMEM (NSTAGE * STG_B)   // 81920 bytes

template<bool HOUT>
__device__ __forceinline__
void gemm_body(const __half* __restrict__ A, const __half* __restrict__ W,
               void* __restrict__ Cv, bool rope, int m0, int n0)
{
    extern __shared__ char dsm[];
    const uint32_t sb = smem_u32(dsm);

    const int tid = threadIdx.x;
    const int wid = tid >> 5;
    const int lid = tid & 31;
    const int wm  = wid >> 1;
    const int wn  = wid & 1;

    const int r    = tid >> 1;
    const int side = tid & 1;
    const __half* Ap = A + (size_t)(m0 + r) * DMODEL + side * 16;
    const __half* Wp = W + (size_t)(n0 + r) * DMODEL + side * 16;
    const uint32_t dA = sb + (uint32_t)(r * (LDS_ROW * 2) + side * 32);
    const uint32_t dW = dA + STG_A_B;

    auto issue = [&](int c) {
        const uint32_t so = (uint32_t)((c & (NSTAGE - 1)) * STG_B);
        const __half* ga = Ap + c * BK;
        const __half* gw = Wp + c * BK;
        CP_ASYNC16(dA + so,      ga);
        CP_ASYNC16(dA + so + 16, ga + 8);
        CP_ASYNC16(dW + so,      gw);
        CP_ASYNC16(dW + so + 16, gw + 8);
        CP_COMMIT();
    };

    uint32_t offA[2], offB[4];
#pragma unroll
    for (int mt = 0; mt < 2; mt++) {
        const int row = wm * 32 + mt * 16 + (lid & 15);
        const int col = (lid >> 4) << 3;
        offA[mt] = (uint32_t)((row * LDS_ROW + col) * 2);
    }
#pragma unroll
    for (int nb = 0; nb < 4; nb++) {
        const int row = wn * 64 + nb * 16 + (lid & 7) + ((lid & 16) ? 8 : 0);
        const int col = (lid & 8) ? 8 : 0;
        offB[nb] = (uint32_t)((row * LDS_ROW + col) * 2 + STG_A_B);
    }

    float acc[2][8][4];
#pragma unroll
    for (int mt = 0; mt < 2; mt++)
#pragma unroll
        for (int nt = 0; nt < 8; nt++)
#pragma unroll
            for (int i = 0; i < 4; i++) acc[mt][nt][i] = 0.f;

    issue(0); issue(1); issue(2);

    for (int c = 0; c < NCH; c++) {
        CP_WAIT(2);
        __syncthreads();
        if (c + 3 < NCH) issue(c + 3);

        const uint32_t st = sb + (uint32_t)((c & (NSTAGE - 1)) * STG_B);
#pragma unroll
        for (int ks = 0; ks < 2; ks++) {
            const uint32_t kso = (uint32_t)(ks * 32);
            uint32_t a[2][4], b[4][4];
#pragma unroll
            for (int mt = 0; mt < 2; mt++)
                ldsm_x4(st + offA[mt] + kso, a[mt][0], a[mt][1], a[mt][2], a[mt][3]);
#pragma unroll
            for (int nb = 0; nb < 4; nb++)
                ldsm_x4(st + offB[nb] + kso, b[nb][0], b[nb][1], b[nb][2], b[nb][3]);
#pragma unroll
            for (int mt = 0; mt < 2; mt++)
#pragma unroll
                for (int nb = 0; nb < 4; nb++) {
                    mma16816(acc[mt][2 * nb],     a[mt], b[nb][0], b[nb][1]);
                    mma16816(acc[mt][2 * nb + 1], a[mt], b[nb][2], b[nb][3]);
                }
        }
    }

    // ---- epilogue (+RoPE); even/odd col pair lives inside one thread ----
    const int qr = lid >> 2;
    const int qc = (lid & 3) * 2;

    float inv[8];
    if (rope) {
#pragma unroll
        for (int nt = 0; nt < 8; nt++) {
            const int d = wn * 64 + nt * 8 + qc;
            inv[nt] = powf(10000.f, -(float)d * (1.f / 128.f));
        }
    }

#pragma unroll
    for (int mt = 0; mt < 2; mt++) {
#pragma unroll
        for (int h = 0; h < 2; h++) {
            const int m = m0 + wm * 32 + mt * 16 + qr + h * 8;
            const float pos = (float)(m & (SEQ - 1));
#pragma unroll
            for (int nt = 0; nt < 8; nt++) {
                float e = acc[mt][nt][2 * h + 0];
                float o = acc[mt][nt][2 * h + 1];
                if (rope) {
                    float sn, cs;
                    sincosf(pos * inv[nt], &sn, &cs);
                    const float e2 = e * cs - o * sn;
                    o = e * sn + o * cs;
                    e = e2;
                }
                const int col = n0 + wn * 64 + nt * 8 + qc;
                if (HOUT) {
                    __half2 hv = __floats2half2_rn(e, o);
                    *reinterpret_cast<__half2*>(
                        (__half*)Cv + (size_t)m * DMODEL + col) = hv;
                } else {
                    *(float2*)((float*)Cv + (size_t)m * DMODEL + col) =
                        make_float2(e, o);
                }
            }
        }
    }
}

// Fused QKV: blockIdx.z selects weight/output; RoPE for Q (z=0) and K (z=1).
__global__ __launch_bounds__(256, 2)
void gemm_qkv(const __half* __restrict__ A,
              const __half* __restrict__ W0, const __half* __restrict__ W1,
              const __half* __restrict__ W2,
              __half* __restrict__ C0, __half* __restrict__ C1,
              __half* __restrict__ C2)
{
    const int z = blockIdx.z;
    const __half* W = (z == 0) ? W0 : (z == 1) ? W1 : W2;
    __half*       C = (z == 0) ? C0 : (z == 1) ? C1 : C2;
    gemm_body<true>(A, W, C, z < 2, blockIdx.y * 128, blockIdx.x * 128);
}

// Output projection: fp16 in, fp32 out, no RoPE.
__global__ __launch_bounds__(256, 2)
void gemm_out(const __half* __restrict__ A, const __half* __restrict__ W,
              float* __restrict__ C)
{
    gemm_body<false>(A, W, C, false, blockIdx.y * 128, blockIdx.x * 128);
}

// ---------------------------------------------------------------------------
// HMMA flash attention (causal). Grid (SEQ/128, NHEADS, BATCH), 256 threads.
// 8 warps x 16 query rows; KV tiles of 64, double-buffered via cp.async.
// S-frag -> P A-frag register identity (no P through smem). fp32 softmax.
// ---------------------------------------------------------------------------
#define AT_STRIDE  136                      // halves per row (128 + 8)
#define AT_ROW_B   (AT_STRIDE * 2)          // 272 bytes
#define AT_STAGE_B (128 * AT_ROW_B)         // 34816 bytes (K rows 0-63, V 64-127)
#define ATTN_SMEM  (2 * AT_STAGE_B)         // 69632 bytes

__global__ __launch_bounds__(256)
void attn_hmma(const __half* __restrict__ Q, const __half* __restrict__ K,
               const __half* __restrict__ V, __half* __restrict__ O)
{
    extern __shared__ char dsm[];
    __half* sKV = (__half*)dsm;
    const uint32_t sb = smem_u32(dsm);

    const int tid = threadIdx.x;
    const int wid = tid >> 5;
    const int lid = tid & 31;
    const int qt  = blockIdx.x;
    const int h   = blockIdx.y;
    const int b   = blockIdx.z;
    const int q0  = qt * 128;

    const size_t base = (size_t)b * SEQ * DMODEL + (size_t)h * DHEAD;
    const float K1 = 0.08838834764831845f * 1.4426950408889634f;  // scale*log2(e)

    // ---- stage Q tile (128x128 half) in stage 0, pull A-frags ----
    for (int i = tid; i < 128 * 16; i += 256) {
        const int rr = i >> 4;
        const int db = i & 15;
        *(uint4*)&sKV[rr * AT_STRIDE + db * 8] =
            *(const uint4*)&Q[base + (size_t)(q0 + rr) * DMODEL + db * 8];
    }
    __syncthreads();

    uint32_t qf[8][4];
    {
        const int arow = wid * 16 + (lid & 15);
        const int acol = (lid >> 4) << 3;
#pragma unroll
        for (int kst = 0; kst < 8; kst++)
            ldsm_x4(sb + (uint32_t)((arow * AT_STRIDE + kst * 16 + acol) * 2),
                    qf[kst][0], qf[kst][1], qf[kst][2], qf[kst][3]);
    }
    __syncthreads();   // all Q frags read before stage 0 is overwritten by KV

    auto issueKV = [&](int kt, int s) {
        const uint32_t stg = sb + (uint32_t)(s * AT_STAGE_B);
        const int kv0 = kt * 64;
#pragma unroll
        for (int j = 0; j < 4; j++) {
            const int idx = tid + j * 256;    // 0..1023
            const int c   = idx >> 4;         // kv row 0..63
            const int db  = idx & 15;         // 16B chunk
            const size_t src = base + (size_t)(kv0 + c) * DMODEL + db * 8;
            CP_ASYNC16(stg + (uint32_t)(c * AT_ROW_B + db * 16),        &K[src]);
            CP_ASYNC16(stg + (uint32_t)((64 + c) * AT_ROW_B + db * 16), &V[src]);
        }
        CP_COMMIT();
    };

    float acc[16][4];
#pragma unroll
    for (int nt = 0; nt < 16; nt++)
#pragma unroll
        for (int i = 0; i < 4; i++) acc[nt][i] = 0.f;
    float mrow0 = -1e30f, mrow1 = -1e30f, lrow0 = 0.f, lrow1 = 0.f;

    const int r0  = lid >> 2;
    const int qcl = (lid & 3) * 2;
    const int wrow_min = q0 + wid * 16;
    const int ntiles = 2 * qt + 2;

    issueKV(0, 0);

    for (int kt = 0; kt < ntiles; kt++) {
        const int s   = kt & 1;
        const int kv0 = kt * 64;

        if (kt + 1 < ntiles) { issueKV(kt + 1, s ^ 1); CP_WAIT(1); }
        else                 { CP_WAIT(0); }
        __syncthreads();

        if (kv0 <= wrow_min + 15) {
            const uint32_t stg = sb + (uint32_t)(s * AT_STAGE_B);

            // ---- S = Q K^T (16x64 per warp) ----
            float sc[8][4];
#pragma unroll
            for (int nt = 0; nt < 8; nt++)
#pragma unroll
                for (int i = 0; i < 4; i++) sc[nt][i] = 0.f;

#pragma unroll
            for (int kst = 0; kst < 8; kst++) {
#pragma unroll
                for (int np = 0; np < 4; np++) {
                    uint32_t b0, b1, b2, b3;
                    const int krow = np * 16 + (lid & 7) + ((lid & 16) ? 8 : 0);
                    const int kcol = kst * 16 + ((lid & 8) ? 8 : 0);
                    ldsm_x4(stg + (uint32_t)((krow * AT_STRIDE + kcol) * 2),
                            b0, b1, b2, b3);
                    mma16816(sc[2 * np],     qf[kst], b0, b1);
                    mma16816(sc[2 * np + 1], qf[kst], b2, b3);
                }
            }

            // ---- causal mask (only near-diagonal warp-tiles) ----
            const int row0 = wrow_min + r0;
            const int row1 = row0 + 8;
            if (kv0 + 63 > wrow_min) {
#pragma unroll
                for (int nt = 0; nt < 8; nt++) {
                    const int col = kv0 + nt * 8 + qcl;
                    if (col     > row0) sc[nt][0] = -1e30f;
                    if (col + 1 > row0) sc[nt][1] = -1e30f;
                    if (col     > row1) sc[nt][2] = -1e30f;
                    if (col + 1 > row1) sc[nt][3] = -1e30f;
                }
            }

            // ---- online softmax (quad reduce over lanes sharing a row) ----
            float m0 = -1e30f, m1 = -1e30f;
#pragma unroll
            for (int nt = 0; nt < 8; nt++) {
                m0 = fmaxf(m0, fmaxf(sc[nt][0], sc[nt][1]));
                m1 = fmaxf(m1, fmaxf(sc[nt][2], sc[nt][3]));
            }
            m0 = fmaxf(m0, __shfl_xor_sync(0xffffffffu, m0, 1));
            m0 = fmaxf(m0, __shfl_xor_sync(0xffffffffu, m0, 2));
            m1 = fmaxf(m1, __shfl_xor_sync(0xffffffffu, m1, 1));
            m1 = fmaxf(m1, __shfl_xor_sync(0xffffffffu, m1, 2));

            const float mn0 = fmaxf(mrow0, m0);
            const float mn1 = fmaxf(mrow1, m1);
            const float al0 = fast_exp2((mrow0 - mn0) * K1);
            const float al1 = fast_exp2((mrow1 - mn1) * K1);
            mrow0 = mn0; mrow1 = mn1;
            const float nk0 = mn0 * K1;
            const float nk1 = mn1 * K1;

            float rs0 = 0.f, rs1 = 0.f;
            uint32_t ph[8][2];
#pragma unroll
            for (int nt = 0; nt < 8; nt++) {
                const float p0 = fast_exp2(fmaf(sc[nt][0], K1, -nk0));
                const float p1 = fast_exp2(fmaf(sc[nt][1], K1, -nk0));
                const float p2 = fast_exp2(fmaf(sc[nt][2], K1, -nk1));
                const float p3 = fast_exp2(fmaf(sc[nt][3], K1, -nk1));
                rs0 += p0 + p1;
                rs1 += p2 + p3;
                __half2 h0 = __floats2half2_rn(p0, p1);
                __half2 h1 = __floats2half2_rn(p2, p3);
                ph[nt][0] = *reinterpret_cast<uint32_t*>(&h0);
                ph[nt][1] = *reinterpret_cast<uint32_t*>(&h1);
            }
            rs0 += __shfl_xor_sync(0xffffffffu, rs0, 1);
            rs0 += __shfl_xor_sync(0xffffffffu, rs0, 2);
            rs1 += __shfl_xor_sync(0xffffffffu, rs1, 1);
            rs1 += __shfl_xor_sync(0xffffffffu, rs1, 2);
            lrow0 = lrow0 * al0 + rs0;
            lrow1 = lrow1 * al1 + rs1;

#pragma unroll
            for (int nt = 0; nt < 16; nt++) {
                acc[nt][0] *= al0; acc[nt][1] *= al0;
                acc[nt][2] *= al1; acc[nt][3] *= al1;
            }

            // ---- O += P V (P A-frags straight from S fragments) ----
#pragma unroll
            for (int kc = 0; kc < 4; kc++) {
                uint32_t a[4] = { ph[2 * kc][0], ph[2 * kc][1],
                                  ph[2 * kc + 1][0], ph[2 * kc + 1][1] };
#pragma unroll
                for (int dp = 0; dp < 8; dp++) {
                    uint32_t v0, v1, v2, v3;
                    const int vrow = 64 + kc * 16 + (lid & 7) + ((lid & 8) ? 8 : 0);
                    const int vcol = dp * 16 + ((lid & 16) ? 8 : 0);
                    ldsm_x4_t(stg + (uint32_t)((vrow * AT_STRIDE + vcol) * 2),
                              v0, v1, v2, v3);
                    mma16816(acc[2 * dp],     a, v0, v1);
                    mma16816(acc[2 * dp + 1], a, v2, v3);
                }
            }
        }
        __syncthreads();   // all warps done with stage s before it is rewritten
    }

    // ---- normalize + fp16 store ----
    const float inv0 = 1.f / lrow0;
    const float inv1 = 1.f / lrow1;
    const int gr0 = q0 + wid * 16 + r0;
    __half* o0 = O + base + (size_t)gr0 * DMODEL;
    __half* o1 = O + base + (size_t)(gr0 + 8) * DMODEL;
#pragma unroll
    for (int nt = 0; nt < 16; nt++) {
        const int col = nt * 8 + qcl;
        __half2 h0 = __floats2half2_rn(acc[nt][0] * inv0, acc[nt][1] * inv0);
        __half2 h1 = __floats2half2_rn(acc[nt][2] * inv1, acc[nt][3] * inv1);
        *reinterpret_cast<__half2*>(o0 + col) = h0;
        *reinterpret_cast<__half2*>(o1 + col) = h1;
    }
}

// ---------------------------------------------------------------------------
// Launch
// ---------------------------------------------------------------------------
extern "C" void kernel_launch(void* const* d_in, const int* in_sizes, int n_in,
                              void* d_out, int out_size)
{
    const float* x  = (const float*)d_in[0];
    const float* wq = (const float*)d_in[1];
    const float* wk = (const float*)d_in[2];
    const float* wv = (const float*)d_in[3];
    const float* wo = (const float*)d_in[4];
    float* out = (float*)d_out;

    __half *xh, *wqh, *wkh, *wvh, *woh, *qh, *kh, *vh, *aoh;
    cudaGetSymbolAddress((void**)&xh,  g_xh);
    cudaGetSymbolAddress((void**)&wqh, g_wqh);
    cudaGetSymbolAddress((void**)&wkh, g_wkh);
    cudaGetSymbolAddress((void**)&wvh, g_wvh);
    cudaGetSymbolAddress((void**)&woh, g_woh);
    cudaGetSymbolAddress((void**)&qh,  g_qh);
    cudaGetSymbolAddress((void**)&kh,  g_kh);
    cudaGetSymbolAddress((void**)&vh,  g_vh);
    cudaGetSymbolAddress((void**)&aoh, g_aoh);

    cudaFuncSetAttribute(gemm_qkv,
                         cudaFuncAttributeMaxDynamicSharedMemorySize, GEMM_SMEM);
    cudaFuncSetAttribute(gemm_out,
                         cudaFuncAttributeMaxDynamicSharedMemorySize, GEMM_SMEM);
    cudaFuncSetAttribute(attn_hmma,
                         cudaFuncAttributeMaxDynamicSharedMemorySize, ATTN_SMEM);

    // ---- one fused fp32 -> fp16 conversion launch (x + 4 weights) ----
    cvt_all<<<dim3(MTOT * DMODEL / 2048, 5), 256>>>(
        x, wq, wk, wv, wo, xh, wqh, wkh, wvh, woh);

    // ---- fused Q/K/V projections (z selects operand; RoPE on z<2) ----
    gemm_qkv<<<dim3(DMODEL / 128, MTOT / 128, 3), 256, GEMM_SMEM>>>(
        xh, wqh, wkh, wvh, qh, kh, vh);

    attn_hmma<<<dim3(SEQ / 128, NHEADS, BATCH), 256, ATTN_SMEM>>>(qh, kh, vh, aoh);

    gemm_out<<<dim3(DMODEL / 128, MTOT / 128), 256, GEMM_SMEM>>>(aoh, woh, out);
}